// round 7
// baseline (speedup 1.0000x reference)
#include <cuda_runtime.h>
#include <cuda_bf16.h>

// ---------------- problem constants ----------------
#define BB   64
#define NNN  197
#define CC   768
#define HHH  12
#define GHH  2
#define HRR  6
#define DD   64
#define TOTH 16          // 2*GH + H
#define QKVN 1024        // TOTH * D
#define SCALE 0.125f
#define NPAD 199         // padded N for smem rows (stride 199 % 32 = 7, conflict-friendly)
#define NT   4           // query rows per attention CTA

#define MROWS (BB*NNN)   // 12608

// ---------------- device scratch (no allocations allowed) ----------------
__device__ float g_q [BB*GHH*NNN*DD];    // (B,GH,N,D)
__device__ float g_k [BB*GHH*NNN*DD];    // (B,GH,N,D)
__device__ float g_v [BB*HHH*NNN*DD];    // (B,H ,N,D)
__device__ float g_mw[NNN*NNN*HHH];      // (N,N,H)  h fastest
__device__ float g_att[BB*NNN*CC];       // (B,N,C) pre-proj attention output

// ---------------- SGEMM: 128x128 tile, 16-deep K, 256 thr, 8x8 per thread ---
// EPI==0: C[row, col] = acc + bias[col]  (plain, writes C)
// EPI==1: scatter qkv columns into g_q / g_k / g_v (C unused)
template<int EPI>
__global__ __launch_bounds__(256)
void sgemm128(const float* __restrict__ A, const float* __restrict__ Bw,
              const float* __restrict__ bias, float* __restrict__ C,
              int M, int Nc, int K)
{
    __shared__ float As[16*128];   // transposed: As[k][i]
    __shared__ float Bs[16*128];   // Bs[k][j]

    const int tid = threadIdx.x;
    const int rowBase = blockIdx.y * 128;
    const int colBase = blockIdx.x * 128;

    const int a_r = tid >> 2;            // 0..63
    const int a_c = (tid & 3) << 2;      // 0,4,8,12
    const int b_r = tid >> 5;            // 0..7
    const int b_c = (tid & 31) << 2;     // 0..124

    const int tx = tid & 15;             // col group
    const int ty = tid >> 4;             // row group

    float acc[8][8];
    #pragma unroll
    for (int i = 0; i < 8; i++)
        #pragma unroll
        for (int j = 0; j < 8; j++) acc[i][j] = 0.f;

    for (int k0 = 0; k0 < K; k0 += 16) {
        #pragma unroll
        for (int p = 0; p < 2; p++) {
            int r  = a_r + p*64;
            int gr = rowBase + r;
            float4 av = (gr < M) ? *(const float4*)(A + (size_t)gr*K + k0 + a_c)
                                 : make_float4(0.f,0.f,0.f,0.f);
            As[(a_c+0)*128 + r] = av.x;
            As[(a_c+1)*128 + r] = av.y;
            As[(a_c+2)*128 + r] = av.z;
            As[(a_c+3)*128 + r] = av.w;
        }
        #pragma unroll
        for (int p = 0; p < 2; p++) {
            int r = b_r + p*8;
            *(float4*)(Bs + r*128 + b_c) =
                *(const float4*)(Bw + (size_t)(k0 + r)*Nc + colBase + b_c);
        }
        __syncthreads();

        #pragma unroll
        for (int kk = 0; kk < 16; kk++) {
            float ra[8], rb[8];
            #pragma unroll
            for (int i = 0; i < 8; i++) ra[i] = As[kk*128 + ty*8 + i];
            #pragma unroll
            for (int j = 0; j < 8; j++) rb[j] = Bs[kk*128 + tx*8 + j];
            #pragma unroll
            for (int i = 0; i < 8; i++)
                #pragma unroll
                for (int j = 0; j < 8; j++)
                    acc[i][j] = fmaf(ra[i], rb[j], acc[i][j]);
        }
        __syncthreads();
    }

    #pragma unroll
    for (int i = 0; i < 8; i++) {
        int gr = rowBase + ty*8 + i;
        if (gr < M) {
            int bidx = 0, n = 0;
            if (EPI == 1) { bidx = gr / NNN; n = gr % NNN; }
            #pragma unroll
            for (int j = 0; j < 8; j++) {
                int gc = colBase + tx*8 + j;
                float val = acc[i][j] + bias[gc];
                if (EPI == 0) {
                    C[(size_t)gr*Nc + gc] = val;
                } else {
                    int t = gc >> 6, d = gc & 63;
                    if (t < GHH)
                        g_q[(((size_t)bidx*GHH + t)*NNN + n)*DD + d] = val;
                    else if (t < 2*GHH)
                        g_k[(((size_t)bidx*GHH + (t-GHH))*NNN + n)*DD + d] = val;
                    else
                        g_v[(((size_t)bidx*HHH + (t-2*GHH))*NNN + n)*DD + d] = val;
                }
            }
        }
    }
}

// ---------------- mask weights: mw[n,m,h] = masks[n,m,:]@mask_proj[:,h]+base[h]
__global__ void mw_kernel(const float* __restrict__ masks,
                          const float* __restrict__ mproj,
                          const float* __restrict__ mbase)
{
    int idx = blockIdx.x * blockDim.x + threadIdx.x;   // (n*N + m)
    if (idx >= NNN*NNN) return;
    float l0 = masks[(size_t)idx*3 + 0];
    float l1 = masks[(size_t)idx*3 + 1];
    float l2 = masks[(size_t)idx*3 + 2];
    #pragma unroll
    for (int h = 0; h < HHH; h++) {
        g_mw[(size_t)idx*HHH + h] =
            l0*mproj[0*HHH + h] + l1*mproj[1*HHH + h] + l2*mproj[2*HHH + h] + mbase[h];
    }
}

// ---------------- fused attention --------------------------------------------
// CTA = (n-tile of NT rows, batch b). 384 threads = 12 warps.
__global__ __launch_bounds__(384)
void attn_kernel(const float* __restrict__ hpw, const float* __restrict__ hpb)
{
    __shared__ float q_s[NT][GHH][DD];        // 2 KB
    __shared__ float S_s[NT][GHH][NPAD];      // scaled qk dots
    __shared__ float W_s[HHH*HHH];
    __shared__ float hb_s[HHH];
    __shared__ float L_s[NT][HHH][NPAD];      // logits -> probs (in place)

    const int tid  = threadIdx.x;
    const int lane = tid & 31;
    const int warp = tid >> 5;                // 0..11
    const int b    = blockIdx.y;
    const int n0   = blockIdx.x * NT;
    const int nvalid = min(NT, NNN - n0);

    if (tid < HHH*HHH) W_s[tid] = hpw[tid];
    if (tid < HHH)     hb_s[tid] = hpb[tid];

    // load q tile (zero-fill invalid rows -> S becomes 0, logits finite)
    for (int i = tid; i < NT*GHH*DD; i += 384) {
        int nt = i / (GHH*DD), rem = i % (GHH*DD);
        int g = rem / DD, d = rem % DD;
        q_s[nt][g][d] = (nt < nvalid)
            ? g_q[(((size_t)b*GHH + g)*NNN + (n0 + nt))*DD + d] : 0.f;
    }
    __syncthreads();

    // ---- Phase 1a: S[nt][g][m] = SCALE * q[nt,g]·k[b,g,m] ----
    for (int m = warp; m < NNN; m += 12) {
        const float* kb0 = g_k + (((size_t)b*GHH + 0)*NNN + m)*DD;
        const float* kb1 = g_k + (((size_t)b*GHH + 1)*NNN + m)*DD;
        float k00 = kb0[lane], k01 = kb0[lane+32];
        float k10 = kb1[lane], k11 = kb1[lane+32];
        #pragma unroll
        for (int nt = 0; nt < NT; nt++) {
            float p0 = q_s[nt][0][lane]*k00 + q_s[nt][0][lane+32]*k01;
            float p1 = q_s[nt][1][lane]*k10 + q_s[nt][1][lane+32]*k11;
            #pragma unroll
            for (int off = 16; off > 0; off >>= 1) {
                p0 += __shfl_xor_sync(0xffffffffu, p0, off);
                p1 += __shfl_xor_sync(0xffffffffu, p1, off);
            }
            if (lane == 0) {
                S_s[nt][0][m] = p0 * SCALE;
                S_s[nt][1][m] = p1 * SCALE;
            }
        }
    }
    __syncthreads();

    // ---- Phase 1b: per (nt,m) relu(s_g * mw) -> 12x12 head mix -> logits ----
    for (int i = tid; i < NT*NNN; i += 384) {
        int nt = i / NNN, m = i % NNN;
        int n = n0 + nt;
        if (n >= NNN) n = NNN - 1;                 // clamp addr; data already 0 via S
        float s0 = S_s[nt][0][m];
        float s1 = S_s[nt][1][m];
        const float* mwp = g_mw + ((size_t)n*NNN + m)*HHH;
        float r[HHH];
        #pragma unroll
        for (int h = 0; h < HHH; h++) {
            float v = (h < HRR ? s0 : s1) * mwp[h];
            r[h] = v > 0.f ? v : 0.f;
        }
        #pragma unroll
        for (int hp = 0; hp < HHH; hp++) {
            float acc = hb_s[hp];
            #pragma unroll
            for (int h = 0; h < HHH; h++) acc = fmaf(r[h], W_s[h*HHH + hp], acc);
            L_s[nt][hp][m] = acc;
        }
    }
    __syncthreads();

    // ---- Phase 2: softmax over m, one warp per (nt,hp) pair ----
    for (int pair = warp; pair < NT*HHH; pair += 12) {
        int nt = pair / HHH, hp = pair % HHH;
        float* row = L_s[nt][hp];
        float mx = -1e30f;
        for (int m = lane; m < NNN; m += 32) mx = fmaxf(mx, row[m]);
        #pragma unroll
        for (int off = 16; off > 0; off >>= 1)
            mx = fmaxf(mx, __shfl_xor_sync(0xffffffffu, mx, off));
        float sum = 0.f;
        for (int m = lane; m < NNN; m += 32) {
            float e = __expf(row[m] - mx);
            row[m] = e;
            sum += e;
        }
        #pragma unroll
        for (int off = 16; off > 0; off >>= 1)
            sum += __shfl_xor_sync(0xffffffffu, sum, off);
        float inv = 1.f / sum;
        for (int m = lane; m < NNN; m += 32) row[m] *= inv;
    }
    __syncthreads();

    // ---- Phase 3: O[nt][hp][d] = sum_m p[m] * v[b,hp,m,d]; warp = hp ----
    {
        const int hp = warp;
        const float* vb = g_v + (((size_t)b*HHH + hp)*NNN)*DD;
        float acc0[NT], acc1[NT];
        #pragma unroll
        for (int nt = 0; nt < NT; nt++) { acc0[nt] = 0.f; acc1[nt] = 0.f; }
        #pragma unroll 4
        for (int m = 0; m < NNN; m++) {
            float v0 = vb[(size_t)m*DD + lane];
            float v1 = vb[(size_t)m*DD + lane + 32];
            #pragma unroll
            for (int nt = 0; nt < NT; nt++) {
                float p = L_s[nt][hp][m];
                acc0[nt] = fmaf(p, v0, acc0[nt]);
                acc1[nt] = fmaf(p, v1, acc1[nt]);
            }
        }
        for (int nt = 0; nt < nvalid; nt++) {
            float* op = g_att + ((size_t)b*NNN + n0 + nt)*CC + hp*DD;
            op[lane]      = acc0[nt];
            op[lane + 32] = acc1[nt];
        }
    }
}

// ---------------- launcher ----------------------------------------------------
extern "C" void kernel_launch(void* const* d_in, const int* in_sizes, int n_in,
                              void* d_out, int out_size)
{
    const float* x         = (const float*)d_in[0];
    const float* qkv_w     = (const float*)d_in[1];
    const float* qkv_b     = (const float*)d_in[2];
    const float* masks     = (const float*)d_in[3];
    const float* mask_proj = (const float*)d_in[4];
    const float* mask_base = (const float*)d_in[5];
    const float* hpw       = (const float*)d_in[6];
    const float* hpb       = (const float*)d_in[7];
    const float* proj_w    = (const float*)d_in[8];
    const float* proj_b    = (const float*)d_in[9];
    float* out             = (float*)d_out;

    // resolve scratch symbol for proj-GEMM input (host can't decay __device__ arrays)
    void* att_ptr = nullptr;
    cudaGetSymbolAddress(&att_ptr, g_att);

    const int M = MROWS;  // 12608

    // 1) QKV GEMM + scatter into g_q/g_k/g_v
    {
        dim3 grid(QKVN/128, (M + 127)/128);
        sgemm128<1><<<grid, 256>>>(x, qkv_w, qkv_b, nullptr, M, QKVN, CC);
    }
    // 2) mask weights
    mw_kernel<<<(NNN*NNN + 255)/256, 256>>>(masks, mask_proj, mask_base);
    // 3) fused attention -> g_att
    {
        dim3 grid((NNN + NT - 1)/NT, BB);
        attn_kernel<<<grid, 384>>>(hpw, hpb);
    }
    // 4) output projection -> d_out
    {
        dim3 grid(CC/128, (M + 127)/128);
        sgemm128<0><<<grid, 256>>>((const float*)att_ptr, proj_w, proj_b, out, M, CC, CC);
    }
}

// round 8
// speedup vs baseline: 1.0872x; 1.0872x over previous
#include <cuda_runtime.h>
#include <cuda_bf16.h>

// ---------------- problem constants ----------------
#define BB   64
#define NNN  197
#define CC   768
#define HHH  12
#define GHH  2
#define HRR  6
#define DD   64
#define TOTH 16          // 2*GH + H
#define QKVN 1024        // TOTH * D
#define SCALE 0.125f
#define SP   200         // padded row stride (multiple of 4 -> float4-aligned rows)
#define NT   8           // query rows per attention CTA

#define MROWS (BB*NNN)   // 12608

// ---------------- device scratch (no allocations allowed) ----------------
__device__ float g_q [BB*GHH*NNN*DD];    // (B,GH,N,D)
__device__ float g_k [BB*GHH*NNN*DD];    // (B,GH,N,D)
__device__ float g_v [BB*HHH*NNN*DD];    // (B,H ,N,D)
__device__ float g_mw[NNN*NNN*HHH];      // (N,N,H)  h fastest
__device__ float g_att[BB*NNN*CC];       // (B,N,C) pre-proj attention output

// ---------------- SGEMM: 128x128 tile, K-step 16, 256 thr, 8x8/thread,
// register-prefetch double buffering of the global loads.
// EPI==0: C = acc + bias   EPI==1: scatter into g_q/g_k/g_v
template<int EPI>
__global__ __launch_bounds__(256, 2)
void sgemm128(const float* __restrict__ A, const float* __restrict__ Bw,
              const float* __restrict__ bias, float* __restrict__ C,
              int M, int Nc, int K)
{
    __shared__ float As[16*128];   // transposed: As[k][i]
    __shared__ float Bs[16*128];   // Bs[k][j]

    const int tid = threadIdx.x;
    const int rowBase = blockIdx.y * 128;
    const int colBase = blockIdx.x * 128;

    const int a_r = tid >> 2;            // 0..63
    const int a_c = (tid & 3) << 2;      // 0,4,8,12
    const int b_r = tid >> 5;            // 0..7
    const int b_c = (tid & 31) << 2;     // 0..124

    const int tx = tid & 15;
    const int ty = tid >> 4;

    float acc[8][8];
    #pragma unroll
    for (int i = 0; i < 8; i++)
        #pragma unroll
        for (int j = 0; j < 8; j++) acc[i][j] = 0.f;

    float4 aReg[2], bReg[2];

    // prologue: prefetch k0 = 0
    #pragma unroll
    for (int p = 0; p < 2; p++) {
        int gr = rowBase + a_r + p*64;
        aReg[p] = (gr < M) ? *(const float4*)(A + (size_t)gr*K + a_c)
                           : make_float4(0.f,0.f,0.f,0.f);
        bReg[p] = *(const float4*)(Bw + (size_t)(b_r + p*8)*Nc + colBase + b_c);
    }

    for (int k0 = 0; k0 < K; k0 += 16) {
        // commit prefetched tile to smem
        #pragma unroll
        for (int p = 0; p < 2; p++) {
            int r = a_r + p*64;
            As[(a_c+0)*128 + r] = aReg[p].x;
            As[(a_c+1)*128 + r] = aReg[p].y;
            As[(a_c+2)*128 + r] = aReg[p].z;
            As[(a_c+3)*128 + r] = aReg[p].w;
            *(float4*)(Bs + (b_r + p*8)*128 + b_c) = bReg[p];
        }
        __syncthreads();

        // prefetch next tile (overlaps with compute below)
        if (k0 + 16 < K) {
            #pragma unroll
            for (int p = 0; p < 2; p++) {
                int gr = rowBase + a_r + p*64;
                aReg[p] = (gr < M) ? *(const float4*)(A + (size_t)gr*K + k0 + 16 + a_c)
                                   : make_float4(0.f,0.f,0.f,0.f);
                bReg[p] = *(const float4*)(Bw + (size_t)(k0 + 16 + b_r + p*8)*Nc + colBase + b_c);
            }
        }

        #pragma unroll
        for (int kk = 0; kk < 16; kk++) {
            float ra[8], rb[8];
            #pragma unroll
            for (int i = 0; i < 8; i++) ra[i] = As[kk*128 + ty*8 + i];
            #pragma unroll
            for (int j = 0; j < 8; j++) rb[j] = Bs[kk*128 + tx*8 + j];
            #pragma unroll
            for (int i = 0; i < 8; i++)
                #pragma unroll
                for (int j = 0; j < 8; j++)
                    acc[i][j] = fmaf(ra[i], rb[j], acc[i][j]);
        }
        __syncthreads();
    }

    #pragma unroll
    for (int i = 0; i < 8; i++) {
        int gr = rowBase + ty*8 + i;
        if (gr < M) {
            int bidx = 0, n = 0;
            if (EPI == 1) { bidx = gr / NNN; n = gr % NNN; }
            #pragma unroll
            for (int j = 0; j < 8; j++) {
                int gc = colBase + tx*8 + j;
                float val = acc[i][j] + bias[gc];
                if (EPI == 0) {
                    C[(size_t)gr*Nc + gc] = val;
                } else {
                    int t = gc >> 6, d = gc & 63;
                    if (t < GHH)
                        g_q[(((size_t)bidx*GHH + t)*NNN + n)*DD + d] = val;
                    else if (t < 2*GHH)
                        g_k[(((size_t)bidx*GHH + (t-GHH))*NNN + n)*DD + d] = val;
                    else
                        g_v[(((size_t)bidx*HHH + (t-2*GHH))*NNN + n)*DD + d] = val;
                }
            }
        }
    }
}

// ---------------- mask weights: mw[n,m,h] = masks[n,m,:]@mask_proj[:,h]+base[h]
__global__ void mw_kernel(const float* __restrict__ masks,
                          const float* __restrict__ mproj,
                          const float* __restrict__ mbase)
{
    int idx = blockIdx.x * blockDim.x + threadIdx.x;   // (n*N + m)
    if (idx >= NNN*NNN) return;
    float l0 = masks[(size_t)idx*3 + 0];
    float l1 = masks[(size_t)idx*3 + 1];
    float l2 = masks[(size_t)idx*3 + 2];
    #pragma unroll
    for (int h = 0; h < HHH; h++) {
        g_mw[(size_t)idx*HHH + h] =
            l0*mproj[0*HHH + h] + l1*mproj[1*HHH + h] + l2*mproj[2*HHH + h] + mbase[h];
    }
}

// ---------------- fused attention --------------------------------------------
// CTA = (n-tile of NT=8 rows, batch b). 384 threads = 12 warps. Dynamic smem.
#define ATTN_SMEM_FLOATS (NT*GHH*DD + NT*GHH*SP + NT*HHH*SP + 144 + 12)
#define ATTN_SMEM_BYTES  (ATTN_SMEM_FLOATS * 4)

__global__ __launch_bounds__(384, 2)
void attn_kernel(const float* __restrict__ hpw, const float* __restrict__ hpb)
{
    extern __shared__ float sm[];
    float* q_s  = sm;                         // [NT][GHH][DD]
    float* S_s  = q_s + NT*GHH*DD;            // [NT][GHH][SP]
    float* L_s  = S_s + NT*GHH*SP;            // [NT][HHH][SP]
    float* W_s  = L_s + NT*HHH*SP;            // [12*12] (float4-aligned)
    float* hb_s = W_s + 144;                  // [12]

    const int tid  = threadIdx.x;
    const int lane = tid & 31;
    const int warp = tid >> 5;                // 0..11
    const int b    = blockIdx.y;
    const int n0   = blockIdx.x * NT;
    const int nvalid = min(NT, NNN - n0);

    if (tid < 144) W_s[tid]  = hpw[tid];
    if (tid < 12)  hb_s[tid] = hpb[tid];

    // load q tile (zero-fill invalid rows)
    for (int i = tid; i < NT*GHH*DD; i += 384) {
        int nt = i / (GHH*DD), rem = i % (GHH*DD);
        int g = rem / DD, d = rem % DD;
        q_s[(nt*GHH + g)*DD + d] = (nt < nvalid)
            ? g_q[(((size_t)b*GHH + g)*NNN + (n0 + nt))*DD + d] : 0.f;
    }
    __syncthreads();

    // ---- Phase 1a: S[nt][g][m] = SCALE * q[nt,g] . k[b,g,m]  (no shuffles) ----
    for (int idx = tid; idx < NNN*GHH; idx += 384) {
        int m = idx >> 1, g = idx & 1;
        const float4* kp = (const float4*)(g_k + (((size_t)b*GHH + g)*NNN + m)*DD);
        float accm[NT];
        #pragma unroll
        for (int nt = 0; nt < NT; nt++) accm[nt] = 0.f;
        #pragma unroll
        for (int t = 0; t < 16; t++) {
            float4 kv = kp[t];
            #pragma unroll
            for (int nt = 0; nt < NT; nt++) {
                float4 qv = *(const float4*)&q_s[(nt*GHH + g)*DD + t*4];
                accm[nt] = fmaf(qv.x, kv.x, accm[nt]);
                accm[nt] = fmaf(qv.y, kv.y, accm[nt]);
                accm[nt] = fmaf(qv.z, kv.z, accm[nt]);
                accm[nt] = fmaf(qv.w, kv.w, accm[nt]);
            }
        }
        #pragma unroll
        for (int nt = 0; nt < NT; nt++)
            S_s[(nt*GHH + g)*SP + m] = accm[nt] * SCALE;
    }
    __syncthreads();

    // ---- Phase 1b: relu(s_g * mw) -> 12x12 head mix -> logits (vectorized) ----
    for (int i = tid; i < NT*NNN; i += 384) {
        int nt = i / NNN, m = i - nt*NNN;
        int n = n0 + nt;
        if (n >= NNN) n = NNN - 1;            // clamp addr; data already 0 via S
        float s0 = S_s[(nt*GHH + 0)*SP + m];
        float s1 = S_s[(nt*GHH + 1)*SP + m];
        const float4* mwp = (const float4*)(g_mw + ((size_t)n*NNN + m)*HHH);
        float4 mw0 = mwp[0], mw1 = mwp[1], mw2 = mwp[2];
        float r[HHH];
        r[0]  = fmaxf(s0*mw0.x, 0.f); r[1]  = fmaxf(s0*mw0.y, 0.f);
        r[2]  = fmaxf(s0*mw0.z, 0.f); r[3]  = fmaxf(s0*mw0.w, 0.f);
        r[4]  = fmaxf(s0*mw1.x, 0.f); r[5]  = fmaxf(s0*mw1.y, 0.f);
        r[6]  = fmaxf(s1*mw1.z, 0.f); r[7]  = fmaxf(s1*mw1.w, 0.f);
        r[8]  = fmaxf(s1*mw2.x, 0.f); r[9]  = fmaxf(s1*mw2.y, 0.f);
        r[10] = fmaxf(s1*mw2.z, 0.f); r[11] = fmaxf(s1*mw2.w, 0.f);

        const float4* W4 = (const float4*)W_s;
        const float4* hb4 = (const float4*)hb_s;
        float4 a0 = hb4[0], a1 = hb4[1], a2 = hb4[2];
        #pragma unroll
        for (int h = 0; h < HHH; h++) {
            float rh = r[h];
            float4 w0 = W4[h*3 + 0], w1 = W4[h*3 + 1], w2 = W4[h*3 + 2];
            a0.x = fmaf(rh, w0.x, a0.x); a0.y = fmaf(rh, w0.y, a0.y);
            a0.z = fmaf(rh, w0.z, a0.z); a0.w = fmaf(rh, w0.w, a0.w);
            a1.x = fmaf(rh, w1.x, a1.x); a1.y = fmaf(rh, w1.y, a1.y);
            a1.z = fmaf(rh, w1.z, a1.z); a1.w = fmaf(rh, w1.w, a1.w);
            a2.x = fmaf(rh, w2.x, a2.x); a2.y = fmaf(rh, w2.y, a2.y);
            a2.z = fmaf(rh, w2.z, a2.z); a2.w = fmaf(rh, w2.w, a2.w);
        }
        float* Lb = &L_s[(nt*HHH)*SP + m];
        Lb[0*SP] = a0.x; Lb[1*SP]  = a0.y; Lb[2*SP]  = a0.z; Lb[3*SP]  = a0.w;
        Lb[4*SP] = a1.x; Lb[5*SP]  = a1.y; Lb[6*SP]  = a1.z; Lb[7*SP]  = a1.w;
        Lb[8*SP] = a2.x; Lb[9*SP]  = a2.y; Lb[10*SP] = a2.z; Lb[11*SP] = a2.w;
    }
    __syncthreads();

    // ---- Phase 2: softmax over m, one warp per (nt,hp) row ----
    for (int pair = warp; pair < NT*HHH; pair += 12) {
        float* row = &L_s[pair*SP];
        float mx = -1e30f;
        for (int m = lane; m < NNN; m += 32) mx = fmaxf(mx, row[m]);
        #pragma unroll
        for (int off = 16; off > 0; off >>= 1)
            mx = fmaxf(mx, __shfl_xor_sync(0xffffffffu, mx, off));
        float sum = 0.f;
        for (int m = lane; m < NNN; m += 32) {
            float e = __expf(row[m] - mx);
            row[m] = e;
            sum += e;
        }
        #pragma unroll
        for (int off = 16; off > 0; off >>= 1)
            sum += __shfl_xor_sync(0xffffffffu, sum, off);
        float inv = 1.f / sum;
        for (int m = lane; m < NNN; m += 32) row[m] *= inv;
    }
    __syncthreads();

    // ---- Phase 3: O[nt][hp][:] = sum_m p * v[b,hp,m,:]; warp = hp, 4-m unroll ----
    {
        const int hp = warp;
        const float2* vb = (const float2*)(g_v + (((size_t)b*HHH + hp)*NNN)*DD);
        float2 acc[NT];
        #pragma unroll
        for (int nt = 0; nt < NT; nt++) acc[nt] = make_float2(0.f, 0.f);

        for (int m0 = 0; m0 + 4 <= NNN; m0 += 4) {
            float2 v0 = vb[(m0+0)*32 + lane];
            float2 v1 = vb[(m0+1)*32 + lane];
            float2 v2 = vb[(m0+2)*32 + lane];
            float2 v3 = vb[(m0+3)*32 + lane];
            #pragma unroll
            for (int nt = 0; nt < NT; nt++) {
                float4 p = *(const float4*)&L_s[(nt*HHH + hp)*SP + m0];
                acc[nt].x = fmaf(p.x, v0.x, acc[nt].x); acc[nt].y = fmaf(p.x, v0.y, acc[nt].y);
                acc[nt].x = fmaf(p.y, v1.x, acc[nt].x); acc[nt].y = fmaf(p.y, v1.y, acc[nt].y);
                acc[nt].x = fmaf(p.z, v2.x, acc[nt].x); acc[nt].y = fmaf(p.z, v2.y, acc[nt].y);
                acc[nt].x = fmaf(p.w, v3.x, acc[nt].x); acc[nt].y = fmaf(p.w, v3.y, acc[nt].y);
            }
        }
        {   // remainder m = 196
            float2 v0 = vb[196*32 + lane];
            #pragma unroll
            for (int nt = 0; nt < NT; nt++) {
                float p = L_s[(nt*HHH + hp)*SP + 196];
                acc[nt].x = fmaf(p, v0.x, acc[nt].x);
                acc[nt].y = fmaf(p, v0.y, acc[nt].y);
            }
        }
        for (int nt = 0; nt < nvalid; nt++) {
            float2* op = (float2*)(g_att + ((size_t)b*NNN + n0 + nt)*CC + hp*DD);
            op[lane] = acc[nt];
        }
    }
}

// ---------------- launcher ----------------------------------------------------
extern "C" void kernel_launch(void* const* d_in, const int* in_sizes, int n_in,
                              void* d_out, int out_size)
{
    const float* x         = (const float*)d_in[0];
    const float* qkv_w     = (const float*)d_in[1];
    const float* qkv_b     = (const float*)d_in[2];
    const float* masks     = (const float*)d_in[3];
    const float* mask_proj = (const float*)d_in[4];
    const float* mask_base = (const float*)d_in[5];
    const float* hpw       = (const float*)d_in[6];
    const float* hpb       = (const float*)d_in[7];
    const float* proj_w    = (const float*)d_in[8];
    const float* proj_b    = (const float*)d_in[9];
    float* out             = (float*)d_out;

    void* att_ptr = nullptr;
    cudaGetSymbolAddress(&att_ptr, g_att);

    // allow >48KB dynamic smem for the attention kernel (idempotent)
    cudaFuncSetAttribute(attn_kernel, cudaFuncAttributeMaxDynamicSharedMemorySize,
                         ATTN_SMEM_BYTES);

    const int M = MROWS;  // 12608

    // 1) QKV GEMM + scatter into g_q/g_k/g_v
    {
        dim3 grid(QKVN/128, (M + 127)/128);
        sgemm128<1><<<grid, 256>>>(x, qkv_w, qkv_b, nullptr, M, QKVN, CC);
    }
    // 2) mask weights
    mw_kernel<<<(NNN*NNN + 255)/256, 256>>>(masks, mask_proj, mask_base);
    // 3) fused attention -> g_att
    {
        dim3 grid((NNN + NT - 1)/NT, BB);
        attn_kernel<<<grid, 384, ATTN_SMEM_BYTES>>>(hpw, hpb);
    }
    // 4) output projection -> d_out
    {
        dim3 grid(CC/128, (M + 127)/128);
        sgemm128<0><<<grid, 256>>>((const float*)att_ptr, proj_w, proj_b, out, M, CC, CC);
    }
}

// round 10
// speedup vs baseline: 1.3179x; 1.2121x over previous
#include <cuda_runtime.h>
#include <cuda_bf16.h>
#include <cstdint>

// ---------------- problem constants ----------------
#define BB   64
#define NNN  197
#define CC   768
#define HHH  12
#define GHH  2
#define HRR  6
#define DD   64
#define TOTH 16
#define QKVN 1024
#define SCALE 0.125f
#define SP   200
#define NT   8
#define MROWS (BB*NNN)   // 12608

// ---------------- device scratch ----------------
__device__ float g_q [BB*GHH*NNN*DD];
__device__ float g_k [BB*GHH*NNN*DD];
__device__ float g_v [BB*HHH*NNN*DD];
__device__ float g_mw[NNN*NNN*HHH];
__device__ float g_att[BB*NNN*CC];

// split-bf16 operands
__device__ __nv_bfloat16 g_xh[MROWS*CC], g_xl[MROWS*CC];   // x split
__device__ __nv_bfloat16 g_ah[MROWS*CC], g_al[MROWS*CC];   // g_att split
__device__ __nv_bfloat16 g_qwh[QKVN*CC], g_qwl[QKVN*CC];   // qkv_w^T split  [N][K]
__device__ __nv_bfloat16 g_pwh[CC*CC],  g_pwl[CC*CC];      // proj_w^T split [N][K]

// ---------------- split kernels ----------------
__global__ void split_kernel(const float* __restrict__ src,
                             __nv_bfloat16* __restrict__ hi,
                             __nv_bfloat16* __restrict__ lo, int n)
{
    int i = blockIdx.x*blockDim.x + threadIdx.x;
    if (i < n) {
        float v = src[i];
        __nv_bfloat16 h = __float2bfloat16(v);
        hi[i] = h;
        lo[i] = __float2bfloat16(v - __bfloat162float(h));
    }
}

// transpose + split: w is [K][N] row-major -> out [N][K]
__global__ void wsplit_kernel(const float* __restrict__ w,
                              __nv_bfloat16* __restrict__ hiT,
                              __nv_bfloat16* __restrict__ loT, int K, int N)
{
    int i = blockIdx.x*blockDim.x + threadIdx.x;
    if (i < K*N) {
        int k = i / N, n = i - k*N;
        float v = w[i];
        __nv_bfloat16 h = __float2bfloat16(v);
        hiT[(size_t)n*K + k] = h;
        loT[(size_t)n*K + k] = __float2bfloat16(v - __bfloat162float(h));
    }
}

// ---------------- mma.sync split-bf16 GEMM ------------------------------------
// D = Ah*Bh^T + Al*Bh^T + Ah*Bl^T   (B stored [N][K] K-major)
// CTA 128x128, 8 warps (each 64x32), K-step 32, 72 stages total.
// EPI==0: C = D + bias   EPI==1: scatter into g_q/g_k/g_v with bias
#define TGM 128
#define TGN 128
#define KSTEP 32
#define AST 40          // smem row stride (bf16): 32 + 8 pad -> conflict-free frags

__device__ __forceinline__ void mma16816(float* d,
    uint32_t a0, uint32_t a1, uint32_t a2, uint32_t a3,
    uint32_t b0, uint32_t b1)
{
    asm volatile(
        "mma.sync.aligned.m16n8k16.row.col.f32.bf16.bf16.f32 "
        "{%0,%1,%2,%3}, {%4,%5,%6,%7}, {%8,%9}, {%0,%1,%2,%3};"
        : "+f"(d[0]), "+f"(d[1]), "+f"(d[2]), "+f"(d[3])
        : "r"(a0), "r"(a1), "r"(a2), "r"(a3), "r"(b0), "r"(b1));
}

template<int EPI>
__global__ __launch_bounds__(256)
void tgemm(const __nv_bfloat16* __restrict__ Ah, const __nv_bfloat16* __restrict__ Al,
           const __nv_bfloat16* __restrict__ Bh, const __nv_bfloat16* __restrict__ Bl,
           const float* __restrict__ bias, float* __restrict__ C,
           int M, int Nc, int K)
{
    __shared__ __nv_bfloat16 As[TGM*AST];
    __shared__ __nv_bfloat16 Bs[TGN*AST];

    const int tid  = threadIdx.x;
    const int lane = tid & 31;
    const int warp = tid >> 5;                 // 0..7
    const int mw   = warp >> 2;                // 0..1  -> m offset mw*64
    const int nw   = warp & 3;                 // 0..3  -> n offset nw*32
    const int g    = lane >> 2;                // 0..7
    const int tig  = lane & 3;                 // 0..3

    const int rowBase = blockIdx.y * TGM;
    const int colBase = blockIdx.x * TGN;

    const int rr = tid >> 2;                   // 0..63 (loader row)
    const int cc = tid & 3;                    // 0..3  (loader 16B chunk)

    const int kchunks = K / KSTEP;             // 24
    const int nsteps  = 3 * kchunks;           // 72

    float acc[4][4][4];
    #pragma unroll
    for (int i = 0; i < 4; i++)
        #pragma unroll
        for (int j = 0; j < 4; j++)
            #pragma unroll
            for (int t = 0; t < 4; t++) acc[i][j][t] = 0.f;

    uint4 aR[2], bR[2];

    // prologue: prefetch stage 0 (term 0, k0 = 0)
    #pragma unroll
    for (int it = 0; it < 2; it++) {
        int r = rr + it*64;
        int gr = rowBase + r;
        aR[it] = (gr < M) ? *(const uint4*)(Ah + (size_t)gr*K + cc*8)
                          : make_uint4(0u,0u,0u,0u);
        bR[it] = *(const uint4*)(Bh + (size_t)(colBase + r)*K + cc*8);
    }

    for (int s = 0; s < nsteps; s++) {
        // commit prefetched chunks to smem
        #pragma unroll
        for (int it = 0; it < 2; it++) {
            int r = rr + it*64;
            *(uint4*)(As + r*AST + cc*8) = aR[it];
            *(uint4*)(Bs + r*AST + cc*8) = bR[it];
        }
        __syncthreads();

        // prefetch next stage (overlaps compute)
        if (s + 1 < nsteps) {
            int sn = s + 1;
            int term = sn / kchunks;
            int k0 = (sn - term*kchunks) * KSTEP;
            const __nv_bfloat16* Asrc = (term == 1) ? Al : Ah;
            const __nv_bfloat16* Bsrc = (term == 2) ? Bl : Bh;
            #pragma unroll
            for (int it = 0; it < 2; it++) {
                int r = rr + it*64;
                int gr = rowBase + r;
                aR[it] = (gr < M) ? *(const uint4*)(Asrc + (size_t)gr*K + k0 + cc*8)
                                  : make_uint4(0u,0u,0u,0u);
                bR[it] = *(const uint4*)(Bsrc + (size_t)(colBase + r)*K + k0 + cc*8);
            }
        }

        // compute: two k16 halves
        #pragma unroll
        for (int kh = 0; kh < KSTEP; kh += 16) {
            uint32_t afr[4][4], bfr[4][2];
            #pragma unroll
            for (int i = 0; i < 4; i++) {
                const __nv_bfloat16* pa = As + (mw*64 + i*16 + g)*AST + kh + tig*2;
                afr[i][0] = *(const uint32_t*)(pa);
                afr[i][1] = *(const uint32_t*)(pa + 8*AST);
                afr[i][2] = *(const uint32_t*)(pa + 8);
                afr[i][3] = *(const uint32_t*)(pa + 8*AST + 8);
            }
            #pragma unroll
            for (int j = 0; j < 4; j++) {
                const __nv_bfloat16* pb = Bs + (nw*32 + j*8 + g)*AST + kh + tig*2;
                bfr[j][0] = *(const uint32_t*)(pb);
                bfr[j][1] = *(const uint32_t*)(pb + 8);
            }
            #pragma unroll
            for (int i = 0; i < 4; i++)
                #pragma unroll
                for (int j = 0; j < 4; j++)
                    mma16816(acc[i][j], afr[i][0], afr[i][1], afr[i][2], afr[i][3],
                             bfr[j][0], bfr[j][1]);
        }
        __syncthreads();
    }

    // epilogue: d0,d1 -> (row0+g, gc..gc+1); d2,d3 -> (row0+g+8, gc..gc+1)
    #pragma unroll
    for (int i = 0; i < 4; i++) {
        #pragma unroll
        for (int half = 0; half < 2; half++) {
            int gr = rowBase + mw*64 + i*16 + g + half*8;
            if (gr >= M) continue;
            int bidx = 0, n = 0;
            if (EPI == 1) { bidx = gr / NNN; n = gr - bidx*NNN; }
            #pragma unroll
            for (int j = 0; j < 4; j++) {
                int gc = colBase + nw*32 + j*8 + tig*2;
                float2 v;
                v.x = acc[i][j][half*2 + 0] + bias[gc];
                v.y = acc[i][j][half*2 + 1] + bias[gc + 1];
                if (EPI == 0) {
                    *(float2*)(C + (size_t)gr*Nc + gc) = v;
                } else {
                    int t = gc >> 6, d = gc & 63;
                    if (t < GHH)
                        *(float2*)(g_q + (((size_t)bidx*GHH + t)*NNN + n)*DD + d) = v;
                    else if (t < 2*GHH)
                        *(float2*)(g_k + (((size_t)bidx*GHH + (t-GHH))*NNN + n)*DD + d) = v;
                    else
                        *(float2*)(g_v + (((size_t)bidx*HHH + (t-2*GHH))*NNN + n)*DD + d) = v;
                }
            }
        }
    }
}

// ---------------- mask weights ----------------
__global__ void mw_kernel(const float* __restrict__ masks,
                          const float* __restrict__ mproj,
                          const float* __restrict__ mbase)
{
    int idx = blockIdx.x * blockDim.x + threadIdx.x;
    if (idx >= NNN*NNN) return;
    float l0 = masks[(size_t)idx*3 + 0];
    float l1 = masks[(size_t)idx*3 + 1];
    float l2 = masks[(size_t)idx*3 + 2];
    #pragma unroll
    for (int h = 0; h < HHH; h++) {
        g_mw[(size_t)idx*HHH + h] =
            l0*mproj[0*HHH + h] + l1*mproj[1*HHH + h] + l2*mproj[2*HHH + h] + mbase[h];
    }
}

// ---------------- fused attention (unchanged from R8) -------------------------
#define ATTN_SMEM_FLOATS (NT*GHH*DD + NT*GHH*SP + NT*HHH*SP + 144 + 12)
#define ATTN_SMEM_BYTES  (ATTN_SMEM_FLOATS * 4)

__global__ __launch_bounds__(384, 2)
void attn_kernel(const float* __restrict__ hpw, const float* __restrict__ hpb)
{
    extern __shared__ float sm[];
    float* q_s  = sm;
    float* S_s  = q_s + NT*GHH*DD;
    float* L_s  = S_s + NT*GHH*SP;
    float* W_s  = L_s + NT*HHH*SP;
    float* hb_s = W_s + 144;

    const int tid  = threadIdx.x;
    const int lane = tid & 31;
    const int warp = tid >> 5;
    const int b    = blockIdx.y;
    const int n0   = blockIdx.x * NT;
    const int nvalid = min(NT, NNN - n0);

    if (tid < 144) W_s[tid]  = hpw[tid];
    if (tid < 12)  hb_s[tid] = hpb[tid];

    for (int i = tid; i < NT*GHH*DD; i += 384) {
        int nt = i / (GHH*DD), rem = i % (GHH*DD);
        int g = rem / DD, d = rem % DD;
        q_s[(nt*GHH + g)*DD + d] = (nt < nvalid)
            ? g_q[(((size_t)b*GHH + g)*NNN + (n0 + nt))*DD + d] : 0.f;
    }
    __syncthreads();

    for (int idx = tid; idx < NNN*GHH; idx += 384) {
        int m = idx >> 1, g = idx & 1;
        const float4* kp = (const float4*)(g_k + (((size_t)b*GHH + g)*NNN + m)*DD);
        float accm[NT];
        #pragma unroll
        for (int nt = 0; nt < NT; nt++) accm[nt] = 0.f;
        #pragma unroll
        for (int t = 0; t < 16; t++) {
            float4 kv = kp[t];
            #pragma unroll
            for (int nt = 0; nt < NT; nt++) {
                float4 qv = *(const float4*)&q_s[(nt*GHH + g)*DD + t*4];
                accm[nt] = fmaf(qv.x, kv.x, accm[nt]);
                accm[nt] = fmaf(qv.y, kv.y, accm[nt]);
                accm[nt] = fmaf(qv.z, kv.z, accm[nt]);
                accm[nt] = fmaf(qv.w, kv.w, accm[nt]);
            }
        }
        #pragma unroll
        for (int nt = 0; nt < NT; nt++)
            S_s[(nt*GHH + g)*SP + m] = accm[nt] * SCALE;
    }
    __syncthreads();

    for (int i = tid; i < NT*NNN; i += 384) {
        int nt = i / NNN, m = i - nt*NNN;
        int n = n0 + nt;
        if (n >= NNN) n = NNN - 1;
        float s0 = S_s[(nt*GHH + 0)*SP + m];
        float s1 = S_s[(nt*GHH + 1)*SP + m];
        const float4* mwp = (const float4*)(g_mw + ((size_t)n*NNN + m)*HHH);
        float4 mw0 = mwp[0], mw1 = mwp[1], mw2 = mwp[2];
        float r[HHH];
        r[0]  = fmaxf(s0*mw0.x, 0.f); r[1]  = fmaxf(s0*mw0.y, 0.f);
        r[2]  = fmaxf(s0*mw0.z, 0.f); r[3]  = fmaxf(s0*mw0.w, 0.f);
        r[4]  = fmaxf(s0*mw1.x, 0.f); r[5]  = fmaxf(s0*mw1.y, 0.f);
        r[6]  = fmaxf(s1*mw1.z, 0.f); r[7]  = fmaxf(s1*mw1.w, 0.f);
        r[8]  = fmaxf(s1*mw2.x, 0.f); r[9]  = fmaxf(s1*mw2.y, 0.f);
        r[10] = fmaxf(s1*mw2.z, 0.f); r[11] = fmaxf(s1*mw2.w, 0.f);

        const float4* W4 = (const float4*)W_s;
        const float4* hb4 = (const float4*)hb_s;
        float4 a0 = hb4[0], a1 = hb4[1], a2 = hb4[2];
        #pragma unroll
        for (int h = 0; h < HHH; h++) {
            float rh = r[h];
            float4 w0 = W4[h*3 + 0], w1 = W4[h*3 + 1], w2 = W4[h*3 + 2];
            a0.x = fmaf(rh, w0.x, a0.x); a0.y = fmaf(rh, w0.y, a0.y);
            a0.z = fmaf(rh, w0.z, a0.z); a0.w = fmaf(rh, w0.w, a0.w);
            a1.x = fmaf(rh, w1.x, a1.x); a1.y = fmaf(rh, w1.y, a1.y);
            a1.z = fmaf(rh, w1.z, a1.z); a1.w = fmaf(rh, w1.w, a1.w);
            a2.x = fmaf(rh, w2.x, a2.x); a2.y = fmaf(rh, w2.y, a2.y);
            a2.z = fmaf(rh, w2.z, a2.z); a2.w = fmaf(rh, w2.w, a2.w);
        }
        float* Lb = &L_s[(nt*HHH)*SP + m];
        Lb[0*SP] = a0.x; Lb[1*SP]  = a0.y; Lb[2*SP]  = a0.z; Lb[3*SP]  = a0.w;
        Lb[4*SP] = a1.x; Lb[5*SP]  = a1.y; Lb[6*SP]  = a1.z; Lb[7*SP]  = a1.w;
        Lb[8*SP] = a2.x; Lb[9*SP]  = a2.y; Lb[10*SP] = a2.z; Lb[11*SP] = a2.w;
    }
    __syncthreads();

    for (int pair = warp; pair < NT*HHH; pair += 12) {
        float* row = &L_s[pair*SP];
        float mx = -1e30f;
        for (int m = lane; m < NNN; m += 32) mx = fmaxf(mx, row[m]);
        #pragma unroll
        for (int off = 16; off > 0; off >>= 1)
            mx = fmaxf(mx, __shfl_xor_sync(0xffffffffu, mx, off));
        float sum = 0.f;
        for (int m = lane; m < NNN; m += 32) {
            float e = __expf(row[m] - mx);
            row[m] = e;
            sum += e;
        }
        #pragma unroll
        for (int off = 16; off > 0; off >>= 1)
            sum += __shfl_xor_sync(0xffffffffu, sum, off);
        float inv = 1.f / sum;
        for (int m = lane; m < NNN; m += 32) row[m] *= inv;
    }
    __syncthreads();

    {
        const int hp = warp;
        const float2* vb = (const float2*)(g_v + (((size_t)b*HHH + hp)*NNN)*DD);
        float2 acc[NT];
        #pragma unroll
        for (int nt = 0; nt < NT; nt++) acc[nt] = make_float2(0.f, 0.f);

        for (int m0 = 0; m0 + 4 <= NNN; m0 += 4) {
            float2 v0 = vb[(m0+0)*32 + lane];
            float2 v1 = vb[(m0+1)*32 + lane];
            float2 v2 = vb[(m0+2)*32 + lane];
            float2 v3 = vb[(m0+3)*32 + lane];
            #pragma unroll
            for (int nt = 0; nt < NT; nt++) {
                float4 p = *(const float4*)&L_s[(nt*HHH + hp)*SP + m0];
                acc[nt].x = fmaf(p.x, v0.x, acc[nt].x); acc[nt].y = fmaf(p.x, v0.y, acc[nt].y);
                acc[nt].x = fmaf(p.y, v1.x, acc[nt].x); acc[nt].y = fmaf(p.y, v1.y, acc[nt].y);
                acc[nt].x = fmaf(p.z, v2.x, acc[nt].x); acc[nt].y = fmaf(p.z, v2.y, acc[nt].y);
                acc[nt].x = fmaf(p.w, v3.x, acc[nt].x); acc[nt].y = fmaf(p.w, v3.y, acc[nt].y);
            }
        }
        {
            float2 v0 = vb[196*32 + lane];
            #pragma unroll
            for (int nt = 0; nt < NT; nt++) {
                float p = L_s[(nt*HHH + hp)*SP + 196];
                acc[nt].x = fmaf(p, v0.x, acc[nt].x);
                acc[nt].y = fmaf(p, v0.y, acc[nt].y);
            }
        }
        for (int nt = 0; nt < nvalid; nt++) {
            float2* op = (float2*)(g_att + ((size_t)b*NNN + n0 + nt)*CC + hp*DD);
            op[lane] = acc[nt];
        }
    }
}

// ---------------- launcher ----------------------------------------------------
extern "C" void kernel_launch(void* const* d_in, const int* in_sizes, int n_in,
                              void* d_out, int out_size)
{
    const float* x         = (const float*)d_in[0];
    const float* qkv_w     = (const float*)d_in[1];
    const float* qkv_b     = (const float*)d_in[2];
    const float* masks     = (const float*)d_in[3];
    const float* mask_proj = (const float*)d_in[4];
    const float* mask_base = (const float*)d_in[5];
    const float* hpw       = (const float*)d_in[6];
    const float* hpb       = (const float*)d_in[7];
    const float* proj_w    = (const float*)d_in[8];
    const float* proj_b    = (const float*)d_in[9];
    float* out             = (float*)d_out;

    void *att_p, *xh_p, *xl_p, *ah_p, *al_p, *qwh_p, *qwl_p, *pwh_p, *pwl_p;
    cudaGetSymbolAddress(&att_p, g_att);
    cudaGetSymbolAddress(&xh_p,  g_xh);  cudaGetSymbolAddress(&xl_p,  g_xl);
    cudaGetSymbolAddress(&ah_p,  g_ah);  cudaGetSymbolAddress(&al_p,  g_al);
    cudaGetSymbolAddress(&qwh_p, g_qwh); cudaGetSymbolAddress(&qwl_p, g_qwl);
    cudaGetSymbolAddress(&pwh_p, g_pwh); cudaGetSymbolAddress(&pwl_p, g_pwl);

    cudaFuncSetAttribute(attn_kernel, cudaFuncAttributeMaxDynamicSharedMemorySize,
                         ATTN_SMEM_BYTES);

    const int M = MROWS;               // 12608
    const int MT = (M + TGM - 1)/TGM;  // 99

    // 0) split inputs
    split_kernel<<<(M*CC + 255)/256, 256>>>(x, (__nv_bfloat16*)xh_p, (__nv_bfloat16*)xl_p, M*CC);
    wsplit_kernel<<<(CC*QKVN + 255)/256, 256>>>(qkv_w, (__nv_bfloat16*)qwh_p, (__nv_bfloat16*)qwl_p, CC, QKVN);
    wsplit_kernel<<<(CC*CC + 255)/256, 256>>>(proj_w, (__nv_bfloat16*)pwh_p, (__nv_bfloat16*)pwl_p, CC, CC);
    // 1) QKV GEMM (tensor via mma.sync) + scatter
    {
        dim3 grid(QKVN/TGN, MT);
        tgemm<1><<<grid, 256>>>((const __nv_bfloat16*)xh_p, (const __nv_bfloat16*)xl_p,
                                (const __nv_bfloat16*)qwh_p, (const __nv_bfloat16*)qwl_p,
                                qkv_b, nullptr, M, QKVN, CC);
    }
    // 2) mask weights
    mw_kernel<<<(NNN*NNN + 255)/256, 256>>>(masks, mask_proj, mask_base);
    // 3) fused attention -> g_att
    {
        dim3 grid((NNN + NT - 1)/NT, BB);
        attn_kernel<<<grid, 384, ATTN_SMEM_BYTES>>>(hpw, hpb);
    }
    // 4) split attention output, then output projection (tensor via mma.sync)
    split_kernel<<<(M*CC + 255)/256, 256>>>((const float*)att_p,
                                            (__nv_bfloat16*)ah_p, (__nv_bfloat16*)al_p, M*CC);
    {
        dim3 grid(CC/TGN, MT);
        tgemm<0><<<grid, 256>>>((const __nv_bfloat16*)ah_p, (const __nv_bfloat16*)al_p,
                                (const __nv_bfloat16*)pwh_p, (const __nv_bfloat16*)pwl_p,
                                proj_b, out, M, CC, CC);
    }
}

// round 11
// speedup vs baseline: 1.5068x; 1.1433x over previous
#include <cuda_runtime.h>
#include <cuda_bf16.h>
#include <cstdint>

// ---------------- problem constants ----------------
#define BB   64
#define NNN  197
#define CC   768
#define HHH  12
#define GHH  2
#define HRR  6
#define DD   64
#define TOTH 16
#define QKVN 1024
#define SCALE 0.125f
#define SP   200
#define NT   8
#define MROWS (BB*NNN)   // 12608

// ---------------- device scratch ----------------
__device__ float g_q [BB*GHH*NNN*DD];
__device__ float g_k [BB*GHH*NNN*DD];
__device__ float g_v [BB*HHH*NNN*DD];
__device__ float g_mw[NNN*NNN*HHH];

// split-bf16 operands
__device__ __nv_bfloat16 g_xh[MROWS*CC], g_xl[MROWS*CC];   // x split
__device__ __nv_bfloat16 g_ah[MROWS*CC], g_al[MROWS*CC];   // attention output split (written by attn)
__device__ __nv_bfloat16 g_qwh[QKVN*CC], g_qwl[QKVN*CC];   // qkv_w^T split  [N][K]
__device__ __nv_bfloat16 g_pwh[CC*CC],  g_pwl[CC*CC];      // proj_w^T split [N][K]

// ---------------- split kernels ----------------
__global__ void split_kernel(const float* __restrict__ src,
                             __nv_bfloat16* __restrict__ hi,
                             __nv_bfloat16* __restrict__ lo, int n)
{
    int i = blockIdx.x*blockDim.x + threadIdx.x;
    if (i < n) {
        float v = src[i];
        __nv_bfloat16 h = __float2bfloat16(v);
        hi[i] = h;
        lo[i] = __float2bfloat16(v - __bfloat162float(h));
    }
}

// transpose + split: w is [K][N] row-major -> out [N][K]
__global__ void wsplit_kernel(const float* __restrict__ w,
                              __nv_bfloat16* __restrict__ hiT,
                              __nv_bfloat16* __restrict__ loT, int K, int N)
{
    int i = blockIdx.x*blockDim.x + threadIdx.x;
    if (i < K*N) {
        int k = i / N, n = i - k*N;
        float v = w[i];
        __nv_bfloat16 h = __float2bfloat16(v);
        hiT[(size_t)n*K + k] = h;
        loT[(size_t)n*K + k] = __float2bfloat16(v - __bfloat162float(h));
    }
}

// ---------------- mma.sync split-bf16 GEMM, cp.async double-buffered ----------
// D = Ah*Bh^T + Al*Bh^T + Ah*Bl^T   (B stored [N][K] K-major)
// CTA 128x128, 8 warps (64x32 each), K-step 64, 2-stage cp.async pipeline.
// EPI==0: C = D + bias   EPI==1: scatter into g_q/g_k/g_v with bias
#define TGM 128
#define TGN 128
#define KS2 64
#define AST2 72                       // smem row stride in bf16 (64 + 8 pad)
#define OPER_BYTES (TGM*AST2*2)       // 18432 per operand per stage
#define BUF_BYTES  (2*OPER_BYTES)     // A + B per stage
#define TG2_SMEM   (2*BUF_BYTES)      // 73728 bytes

__device__ __forceinline__ void mma16816(float* d,
    uint32_t a0, uint32_t a1, uint32_t a2, uint32_t a3,
    uint32_t b0, uint32_t b1)
{
    asm volatile(
        "mma.sync.aligned.m16n8k16.row.col.f32.bf16.bf16.f32 "
        "{%0,%1,%2,%3}, {%4,%5,%6,%7}, {%8,%9}, {%0,%1,%2,%3};"
        : "+f"(d[0]), "+f"(d[1]), "+f"(d[2]), "+f"(d[3])
        : "r"(a0), "r"(a1), "r"(a2), "r"(a3), "r"(b0), "r"(b1));
}

template<int EPI>
__global__ __launch_bounds__(256, 2)
void tgemm(const __nv_bfloat16* __restrict__ Ah, const __nv_bfloat16* __restrict__ Al,
           const __nv_bfloat16* __restrict__ Bh, const __nv_bfloat16* __restrict__ Bl,
           const float* __restrict__ bias, float* __restrict__ C,
           int M, int Nc, int K)
{
    extern __shared__ char sm2[];
    __nv_bfloat16* smb = (__nv_bfloat16*)sm2;
    const uint32_t smem_base = (uint32_t)__cvta_generic_to_shared(sm2);

    const int tid  = threadIdx.x;
    const int lane = tid & 31;
    const int warp = tid >> 5;                 // 0..7
    const int mw   = warp >> 2;                // 0..1
    const int nw   = warp & 3;                 // 0..3
    const int g    = lane >> 2;                // 0..7
    const int tig  = lane & 3;                 // 0..3

    const int rowBase = blockIdx.y * TGM;
    const int colBase = blockIdx.x * TGN;

    const int kchunks = K / KS2;               // 12
    const int nsteps  = 3 * kchunks;           // 36

    float acc[4][4][4];
    #pragma unroll
    for (int i = 0; i < 4; i++)
        #pragma unroll
        for (int j = 0; j < 4; j++)
            #pragma unroll
            for (int t = 0; t < 4; t++) acc[i][j][t] = 0.f;

    // async-load one stage: 128 rows x 128B per operand = 1024 chunks of 16B
    auto issue = [&](int s) {
        int term = s / kchunks;
        int k0 = (s - term*kchunks) * KS2;
        const __nv_bfloat16* Asrc = (term == 1) ? Al : Ah;
        const __nv_bfloat16* Bsrc = (term == 2) ? Bl : Bh;
        uint32_t buf = smem_base + (uint32_t)(s & 1) * BUF_BYTES;
        #pragma unroll
        for (int it = 0; it < 4; it++) {
            int c = tid + it*256;              // 0..1023
            int r = c >> 3, col = c & 7;
            int gr = rowBase + r;
            uint32_t ad = buf + (uint32_t)(r*(AST2*2) + col*16);
            const __nv_bfloat16* srcA = Asrc + (size_t)(gr < M ? gr : 0)*K + k0 + col*8;
            int nb = (gr < M) ? 16 : 0;
            asm volatile("cp.async.cg.shared.global [%0], [%1], 16, %2;"
                         :: "r"(ad), "l"(srcA), "r"(nb));
            uint32_t bd = ad + OPER_BYTES;
            const __nv_bfloat16* srcB = Bsrc + (size_t)(colBase + r)*K + k0 + col*8;
            asm volatile("cp.async.cg.shared.global [%0], [%1], 16;"
                         :: "r"(bd), "l"(srcB));
        }
        asm volatile("cp.async.commit_group;" ::: "memory");
    };

    issue(0);

    for (int s = 0; s < nsteps; s++) {
        if (s + 1 < nsteps) {
            issue(s + 1);
            asm volatile("cp.async.wait_group 1;" ::: "memory");
        } else {
            asm volatile("cp.async.wait_group 0;" ::: "memory");
        }
        __syncthreads();

        const __nv_bfloat16* As = smb + (size_t)(s & 1) * (BUF_BYTES/2);
        const __nv_bfloat16* Bs = As + OPER_BYTES/2;

        #pragma unroll
        for (int kh = 0; kh < KS2; kh += 16) {
            uint32_t afr[4][4], bfr[4][2];
            #pragma unroll
            for (int i = 0; i < 4; i++) {
                const __nv_bfloat16* pa = As + (mw*64 + i*16 + g)*AST2 + kh + tig*2;
                afr[i][0] = *(const uint32_t*)(pa);
                afr[i][1] = *(const uint32_t*)(pa + 8*AST2);
                afr[i][2] = *(const uint32_t*)(pa + 8);
                afr[i][3] = *(const uint32_t*)(pa + 8*AST2 + 8);
            }
            #pragma unroll
            for (int j = 0; j < 4; j++) {
                const __nv_bfloat16* pb = Bs + (nw*32 + j*8 + g)*AST2 + kh + tig*2;
                bfr[j][0] = *(const uint32_t*)(pb);
                bfr[j][1] = *(const uint32_t*)(pb + 8);
            }
            #pragma unroll
            for (int i = 0; i < 4; i++)
                #pragma unroll
                for (int j = 0; j < 4; j++)
                    mma16816(acc[i][j], afr[i][0], afr[i][1], afr[i][2], afr[i][3],
                             bfr[j][0], bfr[j][1]);
        }
        __syncthreads();
    }

    // epilogue
    #pragma unroll
    for (int i = 0; i < 4; i++) {
        #pragma unroll
        for (int half = 0; half < 2; half++) {
            int gr = rowBase + mw*64 + i*16 + g + half*8;
            if (gr >= M) continue;
            int bidx = 0, n = 0;
            if (EPI == 1) { bidx = gr / NNN; n = gr - bidx*NNN; }
            #pragma unroll
            for (int j = 0; j < 4; j++) {
                int gc = colBase + nw*32 + j*8 + tig*2;
                float2 v;
                v.x = acc[i][j][half*2 + 0] + bias[gc];
                v.y = acc[i][j][half*2 + 1] + bias[gc + 1];
                if (EPI == 0) {
                    *(float2*)(C + (size_t)gr*Nc + gc) = v;
                } else {
                    int t = gc >> 6, d = gc & 63;
                    if (t < GHH)
                        *(float2*)(g_q + (((size_t)bidx*GHH + t)*NNN + n)*DD + d) = v;
                    else if (t < 2*GHH)
                        *(float2*)(g_k + (((size_t)bidx*GHH + (t-GHH))*NNN + n)*DD + d) = v;
                    else
                        *(float2*)(g_v + (((size_t)bidx*HHH + (t-2*GHH))*NNN + n)*DD + d) = v;
                }
            }
        }
    }
}

// ---------------- mask weights ----------------
__global__ void mw_kernel(const float* __restrict__ masks,
                          const float* __restrict__ mproj,
                          const float* __restrict__ mbase)
{
    int idx = blockIdx.x * blockDim.x + threadIdx.x;
    if (idx >= NNN*NNN) return;
    float l0 = masks[(size_t)idx*3 + 0];
    float l1 = masks[(size_t)idx*3 + 1];
    float l2 = masks[(size_t)idx*3 + 2];
    #pragma unroll
    for (int h = 0; h < HHH; h++) {
        g_mw[(size_t)idx*HHH + h] =
            l0*mproj[0*HHH + h] + l1*mproj[1*HHH + h] + l2*mproj[2*HHH + h] + mbase[h];
    }
}

// ---------------- fused attention (phase 3 now emits split bf16) --------------
#define ATTN_SMEM_FLOATS (NT*GHH*DD + NT*GHH*SP + NT*HHH*SP + 144 + 12)
#define ATTN_SMEM_BYTES  (ATTN_SMEM_FLOATS * 4)

__global__ __launch_bounds__(384, 2)
void attn_kernel(const float* __restrict__ hpw, const float* __restrict__ hpb)
{
    extern __shared__ float sm[];
    float* q_s  = sm;
    float* S_s  = q_s + NT*GHH*DD;
    float* L_s  = S_s + NT*GHH*SP;
    float* W_s  = L_s + NT*HHH*SP;
    float* hb_s = W_s + 144;

    const int tid  = threadIdx.x;
    const int lane = tid & 31;
    const int warp = tid >> 5;
    const int b    = blockIdx.y;
    const int n0   = blockIdx.x * NT;
    const int nvalid = min(NT, NNN - n0);

    if (tid < 144) W_s[tid]  = hpw[tid];
    if (tid < 12)  hb_s[tid] = hpb[tid];

    for (int i = tid; i < NT*GHH*DD; i += 384) {
        int nt = i / (GHH*DD), rem = i % (GHH*DD);
        int g = rem / DD, d = rem % DD;
        q_s[(nt*GHH + g)*DD + d] = (nt < nvalid)
            ? g_q[(((size_t)b*GHH + g)*NNN + (n0 + nt))*DD + d] : 0.f;
    }
    __syncthreads();

    for (int idx = tid; idx < NNN*GHH; idx += 384) {
        int m = idx >> 1, g = idx & 1;
        const float4* kp = (const float4*)(g_k + (((size_t)b*GHH + g)*NNN + m)*DD);
        float accm[NT];
        #pragma unroll
        for (int nt = 0; nt < NT; nt++) accm[nt] = 0.f;
        #pragma unroll
        for (int t = 0; t < 16; t++) {
            float4 kv = kp[t];
            #pragma unroll
            for (int nt = 0; nt < NT; nt++) {
                float4 qv = *(const float4*)&q_s[(nt*GHH + g)*DD + t*4];
                accm[nt] = fmaf(qv.x, kv.x, accm[nt]);
                accm[nt] = fmaf(qv.y, kv.y, accm[nt]);
                accm[nt] = fmaf(qv.z, kv.z, accm[nt]);
                accm[nt] = fmaf(qv.w, kv.w, accm[nt]);
            }
        }
        #pragma unroll
        for (int nt = 0; nt < NT; nt++)
            S_s[(nt*GHH + g)*SP + m] = accm[nt] * SCALE;
    }
    __syncthreads();

    for (int i = tid; i < NT*NNN; i += 384) {
        int nt = i / NNN, m = i - nt*NNN;
        int n = n0 + nt;
        if (n >= NNN) n = NNN - 1;
        float s0 = S_s[(nt*GHH + 0)*SP + m];
        float s1 = S_s[(nt*GHH + 1)*SP + m];
        const float4* mwp = (const float4*)(g_mw + ((size_t)n*NNN + m)*HHH);
        float4 mw0 = mwp[0], mw1 = mwp[1], mw2 = mwp[2];
        float r[HHH];
        r[0]  = fmaxf(s0*mw0.x, 0.f); r[1]  = fmaxf(s0*mw0.y, 0.f);
        r[2]  = fmaxf(s0*mw0.z, 0.f); r[3]  = fmaxf(s0*mw0.w, 0.f);
        r[4]  = fmaxf(s0*mw1.x, 0.f); r[5]  = fmaxf(s0*mw1.y, 0.f);
        r[6]  = fmaxf(s1*mw1.z, 0.f); r[7]  = fmaxf(s1*mw1.w, 0.f);
        r[8]  = fmaxf(s1*mw2.x, 0.f); r[9]  = fmaxf(s1*mw2.y, 0.f);
        r[10] = fmaxf(s1*mw2.z, 0.f); r[11] = fmaxf(s1*mw2.w, 0.f);

        const float4* W4 = (const float4*)W_s;
        const float4* hb4 = (const float4*)hb_s;
        float4 a0 = hb4[0], a1 = hb4[1], a2 = hb4[2];
        #pragma unroll
        for (int h = 0; h < HHH; h++) {
            float rh = r[h];
            float4 w0 = W4[h*3 + 0], w1 = W4[h*3 + 1], w2 = W4[h*3 + 2];
            a0.x = fmaf(rh, w0.x, a0.x); a0.y = fmaf(rh, w0.y, a0.y);
            a0.z = fmaf(rh, w0.z, a0.z); a0.w = fmaf(rh, w0.w, a0.w);
            a1.x = fmaf(rh, w1.x, a1.x); a1.y = fmaf(rh, w1.y, a1.y);
            a1.z = fmaf(rh, w1.z, a1.z); a1.w = fmaf(rh, w1.w, a1.w);
            a2.x = fmaf(rh, w2.x, a2.x); a2.y = fmaf(rh, w2.y, a2.y);
            a2.z = fmaf(rh, w2.z, a2.z); a2.w = fmaf(rh, w2.w, a2.w);
        }
        float* Lb = &L_s[(nt*HHH)*SP + m];
        Lb[0*SP] = a0.x; Lb[1*SP]  = a0.y; Lb[2*SP]  = a0.z; Lb[3*SP]  = a0.w;
        Lb[4*SP] = a1.x; Lb[5*SP]  = a1.y; Lb[6*SP]  = a1.z; Lb[7*SP]  = a1.w;
        Lb[8*SP] = a2.x; Lb[9*SP]  = a2.y; Lb[10*SP] = a2.z; Lb[11*SP] = a2.w;
    }
    __syncthreads();

    for (int pair = warp; pair < NT*HHH; pair += 12) {
        float* row = &L_s[pair*SP];
        float mx = -1e30f;
        for (int m = lane; m < NNN; m += 32) mx = fmaxf(mx, row[m]);
        #pragma unroll
        for (int off = 16; off > 0; off >>= 1)
            mx = fmaxf(mx, __shfl_xor_sync(0xffffffffu, mx, off));
        float sum = 0.f;
        for (int m = lane; m < NNN; m += 32) {
            float e = __expf(row[m] - mx);
            row[m] = e;
            sum += e;
        }
        #pragma unroll
        for (int off = 16; off > 0; off >>= 1)
            sum += __shfl_xor_sync(0xffffffffu, sum, off);
        float inv = 1.f / sum;
        for (int m = lane; m < NNN; m += 32) row[m] *= inv;
    }
    __syncthreads();

    {
        const int hp = warp;
        const float2* vb = (const float2*)(g_v + (((size_t)b*HHH + hp)*NNN)*DD);
        float2 acc[NT];
        #pragma unroll
        for (int nt = 0; nt < NT; nt++) acc[nt] = make_float2(0.f, 0.f);

        for (int m0 = 0; m0 + 4 <= NNN; m0 += 4) {
            float2 v0 = vb[(m0+0)*32 + lane];
            float2 v1 = vb[(m0+1)*32 + lane];
            float2 v2 = vb[(m0+2)*32 + lane];
            float2 v3 = vb[(m0+3)*32 + lane];
            #pragma unroll
            for (int nt = 0; nt < NT; nt++) {
                float4 p = *(const float4*)&L_s[(nt*HHH + hp)*SP + m0];
                acc[nt].x = fmaf(p.x, v0.x, acc[nt].x); acc[nt].y = fmaf(p.x, v0.y, acc[nt].y);
                acc[nt].x = fmaf(p.y, v1.x, acc[nt].x); acc[nt].y = fmaf(p.y, v1.y, acc[nt].y);
                acc[nt].x = fmaf(p.z, v2.x, acc[nt].x); acc[nt].y = fmaf(p.z, v2.y, acc[nt].y);
                acc[nt].x = fmaf(p.w, v3.x, acc[nt].x); acc[nt].y = fmaf(p.w, v3.y, acc[nt].y);
            }
        }
        {
            float2 v0 = vb[196*32 + lane];
            #pragma unroll
            for (int nt = 0; nt < NT; nt++) {
                float p = L_s[(nt*HHH + hp)*SP + 196];
                acc[nt].x = fmaf(p, v0.x, acc[nt].x);
                acc[nt].y = fmaf(p, v0.y, acc[nt].y);
            }
        }
        // write split bf16 directly (hi/lo) -> feeds tgemm<0> without extra pass
        for (int nt = 0; nt < nvalid; nt++) {
            size_t off = ((size_t)b*NNN + n0 + nt)*CC + hp*DD + lane*2;
            float ax = acc[nt].x, ay = acc[nt].y;
            __nv_bfloat16 hx = __float2bfloat16(ax);
            __nv_bfloat16 hy = __float2bfloat16(ay);
            __nv_bfloat162 hv; hv.x = hx; hv.y = hy;
            __nv_bfloat162 lv;
            lv.x = __float2bfloat16(ax - __bfloat162float(hx));
            lv.y = __float2bfloat16(ay - __bfloat162float(hy));
            *(__nv_bfloat162*)(g_ah + off) = hv;
            *(__nv_bfloat162*)(g_al + off) = lv;
        }
    }
}

// ---------------- launcher ----------------------------------------------------
extern "C" void kernel_launch(void* const* d_in, const int* in_sizes, int n_in,
                              void* d_out, int out_size)
{
    const float* x         = (const float*)d_in[0];
    const float* qkv_w     = (const float*)d_in[1];
    const float* qkv_b     = (const float*)d_in[2];
    const float* masks     = (const float*)d_in[3];
    const float* mask_proj = (const float*)d_in[4];
    const float* mask_base = (const float*)d_in[5];
    const float* hpw       = (const float*)d_in[6];
    const float* hpb       = (const float*)d_in[7];
    const float* proj_w    = (const float*)d_in[8];
    const float* proj_b    = (const float*)d_in[9];
    float* out             = (float*)d_out;

    void *xh_p, *xl_p, *ah_p, *al_p, *qwh_p, *qwl_p, *pwh_p, *pwl_p;
    cudaGetSymbolAddress(&xh_p,  g_xh);  cudaGetSymbolAddress(&xl_p,  g_xl);
    cudaGetSymbolAddress(&ah_p,  g_ah);  cudaGetSymbolAddress(&al_p,  g_al);
    cudaGetSymbolAddress(&qwh_p, g_qwh); cudaGetSymbolAddress(&qwl_p, g_qwl);
    cudaGetSymbolAddress(&pwh_p, g_pwh); cudaGetSymbolAddress(&pwl_p, g_pwl);

    cudaFuncSetAttribute(attn_kernel, cudaFuncAttributeMaxDynamicSharedMemorySize,
                         ATTN_SMEM_BYTES);
    cudaFuncSetAttribute(tgemm<0>, cudaFuncAttributeMaxDynamicSharedMemorySize, TG2_SMEM);
    cudaFuncSetAttribute(tgemm<1>, cudaFuncAttributeMaxDynamicSharedMemorySize, TG2_SMEM);

    const int M = MROWS;               // 12608
    const int MT = (M + TGM - 1)/TGM;  // 99

    // 0) split inputs
    split_kernel<<<(M*CC + 255)/256, 256>>>(x, (__nv_bfloat16*)xh_p, (__nv_bfloat16*)xl_p, M*CC);
    wsplit_kernel<<<(CC*QKVN + 255)/256, 256>>>(qkv_w, (__nv_bfloat16*)qwh_p, (__nv_bfloat16*)qwl_p, CC, QKVN);
    wsplit_kernel<<<(CC*CC + 255)/256, 256>>>(proj_w, (__nv_bfloat16*)pwh_p, (__nv_bfloat16*)pwl_p, CC, CC);
    // 1) QKV GEMM (tensor, cp.async pipelined) + scatter
    {
        dim3 grid(QKVN/TGN, MT);
        tgemm<1><<<grid, 256, TG2_SMEM>>>((const __nv_bfloat16*)xh_p, (const __nv_bfloat16*)xl_p,
                                          (const __nv_bfloat16*)qwh_p, (const __nv_bfloat16*)qwl_p,
                                          qkv_b, nullptr, M, QKVN, CC);
    }
    // 2) mask weights
    mw_kernel<<<(NNN*NNN + 255)/256, 256>>>(masks, mask_proj, mask_base);
    // 3) fused attention -> g_ah/g_al (split bf16, direct)
    {
        dim3 grid((NNN + NT - 1)/NT, BB);
        attn_kernel<<<grid, 384, ATTN_SMEM_BYTES>>>(hpw, hpb);
    }
    // 4) output projection (tensor, cp.async pipelined)
    {
        dim3 grid(CC/TGN, MT);
        tgemm<0><<<grid, 256, TG2_SMEM>>>((const __nv_bfloat16*)ah_p, (const __nv_bfloat16*)al_p,
                                          (const __nv_bfloat16*)pwh_p, (const __nv_bfloat16*)pwl_p,
                                          proj_b, out, M, CC, CC);
    }
}

// round 12
// speedup vs baseline: 1.9817x; 1.3152x over previous
#include <cuda_runtime.h>
#include <cuda_bf16.h>
#include <cuda_fp16.h>
#include <cstdint>

// ---------------- problem constants ----------------
#define BB   64
#define NNN  197
#define CC   768
#define HHH  12
#define GHH  2
#define HRR  6
#define DD   64
#define TOTH 16
#define QKVN 1024
#define SCALE 0.125f
#define SP   200
#define NT   4            // query rows per probs CTA
#define NPADR 208         // padded n rows in g_p
#define KPAD 224          // padded m (K dim of PV)
#define MROWS (BB*NNN)    // 12608

// ---------------- device scratch ----------------
__device__ float g_q [BB*GHH*NNN*DD];
__device__ float g_k [BB*GHH*NNN*DD];
__device__ float g_mw[NNN*NNN*HHH];

__device__ __half g_p  [BB*HHH*NPADR*KPAD];   // probs fp16 (K-pad zeroed)
__device__ __half g_vth[BB*HHH*DD*KPAD];      // V^T fp16 hi  [bh][d][m]
__device__ __half g_vtl[BB*HHH*DD*KPAD];      // V^T fp16 lo

// split-bf16 operands
__device__ __nv_bfloat16 g_xh[MROWS*CC], g_xl[MROWS*CC];
__device__ __nv_bfloat16 g_ah[MROWS*CC], g_al[MROWS*CC];
__device__ __nv_bfloat16 g_qwh[QKVN*CC], g_qwl[QKVN*CC];
__device__ __nv_bfloat16 g_pwh[CC*CC],  g_pwl[CC*CC];

// ---------------- split kernels ----------------
__global__ void split_kernel(const float* __restrict__ src,
                             __nv_bfloat16* __restrict__ hi,
                             __nv_bfloat16* __restrict__ lo, int n)
{
    int i = blockIdx.x*blockDim.x + threadIdx.x;
    if (i < n) {
        float v = src[i];
        __nv_bfloat16 h = __float2bfloat16(v);
        hi[i] = h;
        lo[i] = __float2bfloat16(v - __bfloat162float(h));
    }
}

__global__ void wsplit_kernel(const float* __restrict__ w,
                              __nv_bfloat16* __restrict__ hiT,
                              __nv_bfloat16* __restrict__ loT, int K, int N)
{
    int i = blockIdx.x*blockDim.x + threadIdx.x;
    if (i < K*N) {
        int k = i / N, n = i - k*N;
        float v = w[i];
        __nv_bfloat16 h = __float2bfloat16(v);
        hiT[(size_t)n*K + k] = h;
        loT[(size_t)n*K + k] = __float2bfloat16(v - __bfloat162float(h));
    }
}

// ---------------- mma.sync split-bf16 GEMM (unchanged core from R11) ----------
#define TGM 128
#define TGN 128
#define KS2 64
#define AST2 72
#define OPER_BYTES (TGM*AST2*2)
#define BUF_BYTES  (2*OPER_BYTES)
#define TG2_SMEM   (2*BUF_BYTES)

__device__ __forceinline__ void mma16816(float* d,
    uint32_t a0, uint32_t a1, uint32_t a2, uint32_t a3,
    uint32_t b0, uint32_t b1)
{
    asm volatile(
        "mma.sync.aligned.m16n8k16.row.col.f32.bf16.bf16.f32 "
        "{%0,%1,%2,%3}, {%4,%5,%6,%7}, {%8,%9}, {%0,%1,%2,%3};"
        : "+f"(d[0]), "+f"(d[1]), "+f"(d[2]), "+f"(d[3])
        : "r"(a0), "r"(a1), "r"(a2), "r"(a3), "r"(b0), "r"(b1));
}

__device__ __forceinline__ void mma16816h(float* d,
    uint32_t a0, uint32_t a1, uint32_t a2, uint32_t a3,
    uint32_t b0, uint32_t b1)
{
    asm volatile(
        "mma.sync.aligned.m16n8k16.row.col.f32.f16.f16.f32 "
        "{%0,%1,%2,%3}, {%4,%5,%6,%7}, {%8,%9}, {%0,%1,%2,%3};"
        : "+f"(d[0]), "+f"(d[1]), "+f"(d[2]), "+f"(d[3])
        : "r"(a0), "r"(a1), "r"(a2), "r"(a3), "r"(b0), "r"(b1));
}

template<int EPI>
__global__ __launch_bounds__(256, 2)
void tgemm(const __nv_bfloat16* __restrict__ Ah, const __nv_bfloat16* __restrict__ Al,
           const __nv_bfloat16* __restrict__ Bh, const __nv_bfloat16* __restrict__ Bl,
           const float* __restrict__ bias, float* __restrict__ C,
           int M, int Nc, int K)
{
    extern __shared__ char sm2[];
    __nv_bfloat16* smb = (__nv_bfloat16*)sm2;
    const uint32_t smem_base = (uint32_t)__cvta_generic_to_shared(sm2);

    const int tid  = threadIdx.x;
    const int lane = tid & 31;
    const int warp = tid >> 5;
    const int mw   = warp >> 2;
    const int nw   = warp & 3;
    const int g    = lane >> 2;
    const int tig  = lane & 3;

    const int rowBase = blockIdx.y * TGM;
    const int colBase = blockIdx.x * TGN;

    const int kchunks = K / KS2;
    const int nsteps  = 3 * kchunks;

    float acc[4][4][4];
    #pragma unroll
    for (int i = 0; i < 4; i++)
        #pragma unroll
        for (int j = 0; j < 4; j++)
            #pragma unroll
            for (int t = 0; t < 4; t++) acc[i][j][t] = 0.f;

    auto issue = [&](int s) {
        int term = s / kchunks;
        int k0 = (s - term*kchunks) * KS2;
        const __nv_bfloat16* Asrc = (term == 1) ? Al : Ah;
        const __nv_bfloat16* Bsrc = (term == 2) ? Bl : Bh;
        uint32_t buf = smem_base + (uint32_t)(s & 1) * BUF_BYTES;
        #pragma unroll
        for (int it = 0; it < 4; it++) {
            int c = tid + it*256;
            int r = c >> 3, col = c & 7;
            int gr = rowBase + r;
            uint32_t ad = buf + (uint32_t)(r*(AST2*2) + col*16);
            const __nv_bfloat16* srcA = Asrc + (size_t)(gr < M ? gr : 0)*K + k0 + col*8;
            int nb = (gr < M) ? 16 : 0;
            asm volatile("cp.async.cg.shared.global [%0], [%1], 16, %2;"
                         :: "r"(ad), "l"(srcA), "r"(nb));
            uint32_t bd = ad + OPER_BYTES;
            const __nv_bfloat16* srcB = Bsrc + (size_t)(colBase + r)*K + k0 + col*8;
            asm volatile("cp.async.cg.shared.global [%0], [%1], 16;"
                         :: "r"(bd), "l"(srcB));
        }
        asm volatile("cp.async.commit_group;" ::: "memory");
    };

    issue(0);

    for (int s = 0; s < nsteps; s++) {
        if (s + 1 < nsteps) {
            issue(s + 1);
            asm volatile("cp.async.wait_group 1;" ::: "memory");
        } else {
            asm volatile("cp.async.wait_group 0;" ::: "memory");
        }
        __syncthreads();

        const __nv_bfloat16* As = smb + (size_t)(s & 1) * (BUF_BYTES/2);
        const __nv_bfloat16* Bs = As + OPER_BYTES/2;

        #pragma unroll
        for (int kh = 0; kh < KS2; kh += 16) {
            uint32_t afr[4][4], bfr[4][2];
            #pragma unroll
            for (int i = 0; i < 4; i++) {
                const __nv_bfloat16* pa = As + (mw*64 + i*16 + g)*AST2 + kh + tig*2;
                afr[i][0] = *(const uint32_t*)(pa);
                afr[i][1] = *(const uint32_t*)(pa + 8*AST2);
                afr[i][2] = *(const uint32_t*)(pa + 8);
                afr[i][3] = *(const uint32_t*)(pa + 8*AST2 + 8);
            }
            #pragma unroll
            for (int j = 0; j < 4; j++) {
                const __nv_bfloat16* pb = Bs + (nw*32 + j*8 + g)*AST2 + kh + tig*2;
                bfr[j][0] = *(const uint32_t*)(pb);
                bfr[j][1] = *(const uint32_t*)(pb + 8);
            }
            #pragma unroll
            for (int i = 0; i < 4; i++)
                #pragma unroll
                for (int j = 0; j < 4; j++)
                    mma16816(acc[i][j], afr[i][0], afr[i][1], afr[i][2], afr[i][3],
                             bfr[j][0], bfr[j][1]);
        }
        __syncthreads();
    }

    #pragma unroll
    for (int i = 0; i < 4; i++) {
        #pragma unroll
        for (int half = 0; half < 2; half++) {
            int gr = rowBase + mw*64 + i*16 + g + half*8;
            if (gr >= M) continue;
            int bidx = 0, n = 0;
            if (EPI == 1) { bidx = gr / NNN; n = gr - bidx*NNN; }
            #pragma unroll
            for (int j = 0; j < 4; j++) {
                int gc = colBase + nw*32 + j*8 + tig*2;
                float2 v;
                v.x = acc[i][j][half*2 + 0] + bias[gc];
                v.y = acc[i][j][half*2 + 1] + bias[gc + 1];
                if (EPI == 0) {
                    *(float2*)(C + (size_t)gr*Nc + gc) = v;
                } else {
                    int t = gc >> 6, d = gc & 63;
                    if (t < GHH) {
                        *(float2*)(g_q + (((size_t)bidx*GHH + t)*NNN + n)*DD + d) = v;
                    } else if (t < 2*GHH) {
                        *(float2*)(g_k + (((size_t)bidx*GHH + (t-GHH))*NNN + n)*DD + d) = v;
                    } else {
                        // V: write transposed fp16 split  [bh][d][m]
                        int h = t - 2*GHH;
                        size_t bse = ((size_t)(bidx*HHH + h)*DD + d)*KPAD + n;
                        __half h0 = __float2half(v.x);
                        g_vth[bse] = h0;
                        g_vtl[bse] = __float2half(v.x - __half2float(h0));
                        __half h1 = __float2half(v.y);
                        g_vth[bse + KPAD] = h1;
                        g_vtl[bse + KPAD] = __float2half(v.y - __half2float(h1));
                    }
                }
            }
        }
    }
}

// ---------------- mask weights ----------------
__global__ void mw_kernel(const float* __restrict__ masks,
                          const float* __restrict__ mproj,
                          const float* __restrict__ mbase)
{
    int idx = blockIdx.x * blockDim.x + threadIdx.x;
    if (idx >= NNN*NNN) return;
    float l0 = masks[(size_t)idx*3 + 0];
    float l1 = masks[(size_t)idx*3 + 1];
    float l2 = masks[(size_t)idx*3 + 2];
    #pragma unroll
    for (int h = 0; h < HHH; h++) {
        g_mw[(size_t)idx*HHH + h] =
            l0*mproj[0*HHH + h] + l1*mproj[1*HHH + h] + l2*mproj[2*HHH + h] + mbase[h];
    }
}

// ---------------- probs kernel: QK + mask/relu/headmix + softmax -> g_p fp16 --
#define PR_SMEM_FLOATS (NT*GHH*DD + NT*GHH*SP + NT*HHH*SP + 144 + 12)
#define PR_SMEM_BYTES  (PR_SMEM_FLOATS * 4)

__global__ __launch_bounds__(256, 4)
void attn_probs(const float* __restrict__ hpw, const float* __restrict__ hpb)
{
    extern __shared__ float sm[];
    float* q_s  = sm;                         // [NT][GHH][DD]
    float* S_s  = q_s + NT*GHH*DD;            // [NT][GHH][SP]
    float* L_s  = S_s + NT*GHH*SP;            // [NT][HHH][SP]
    float* W_s  = L_s + NT*HHH*SP;            // [144]
    float* hb_s = W_s + 144;                  // [12]

    const int tid  = threadIdx.x;
    const int lane = tid & 31;
    const int warp = tid >> 5;                // 0..7
    const int b    = blockIdx.y;
    const int n0   = blockIdx.x * NT;
    const int nvalid = min(NT, NNN - n0);

    if (tid < 144) W_s[tid]  = hpw[tid];
    if (tid < 12)  hb_s[tid] = hpb[tid];

    for (int i = tid; i < NT*GHH*DD; i += 256) {
        int nt = i / (GHH*DD), rem = i % (GHH*DD);
        int g = rem / DD, d = rem % DD;
        q_s[(nt*GHH + g)*DD + d] = (nt < nvalid)
            ? g_q[(((size_t)b*GHH + g)*NNN + (n0 + nt))*DD + d] : 0.f;
    }
    __syncthreads();

    // Phase 1a
    for (int idx = tid; idx < NNN*GHH; idx += 256) {
        int m = idx >> 1, g = idx & 1;
        const float4* kp = (const float4*)(g_k + (((size_t)b*GHH + g)*NNN + m)*DD);
        float accm[NT];
        #pragma unroll
        for (int nt = 0; nt < NT; nt++) accm[nt] = 0.f;
        #pragma unroll
        for (int t = 0; t < 16; t++) {
            float4 kv = kp[t];
            #pragma unroll
            for (int nt = 0; nt < NT; nt++) {
                float4 qv = *(const float4*)&q_s[(nt*GHH + g)*DD + t*4];
                accm[nt] = fmaf(qv.x, kv.x, accm[nt]);
                accm[nt] = fmaf(qv.y, kv.y, accm[nt]);
                accm[nt] = fmaf(qv.z, kv.z, accm[nt]);
                accm[nt] = fmaf(qv.w, kv.w, accm[nt]);
            }
        }
        #pragma unroll
        for (int nt = 0; nt < NT; nt++)
            S_s[(nt*GHH + g)*SP + m] = accm[nt] * SCALE;
    }
    __syncthreads();

    // Phase 1b
    for (int i = tid; i < NT*NNN; i += 256) {
        int nt = i / NNN, m = i - nt*NNN;
        int n = n0 + nt;
        if (n >= NNN) n = NNN - 1;
        float s0 = S_s[(nt*GHH + 0)*SP + m];
        float s1 = S_s[(nt*GHH + 1)*SP + m];
        const float4* mwp = (const float4*)(g_mw + ((size_t)n*NNN + m)*HHH);
        float4 mw0 = mwp[0], mw1 = mwp[1], mw2 = mwp[2];
        float r[HHH];
        r[0]  = fmaxf(s0*mw0.x, 0.f); r[1]  = fmaxf(s0*mw0.y, 0.f);
        r[2]  = fmaxf(s0*mw0.z, 0.f); r[3]  = fmaxf(s0*mw0.w, 0.f);
        r[4]  = fmaxf(s0*mw1.x, 0.f); r[5]  = fmaxf(s0*mw1.y, 0.f);
        r[6]  = fmaxf(s1*mw1.z, 0.f); r[7]  = fmaxf(s1*mw1.w, 0.f);
        r[8]  = fmaxf(s1*mw2.x, 0.f); r[9]  = fmaxf(s1*mw2.y, 0.f);
        r[10] = fmaxf(s1*mw2.z, 0.f); r[11] = fmaxf(s1*mw2.w, 0.f);

        const float4* W4 = (const float4*)W_s;
        const float4* hb4 = (const float4*)hb_s;
        float4 a0 = hb4[0], a1 = hb4[1], a2 = hb4[2];
        #pragma unroll
        for (int h = 0; h < HHH; h++) {
            float rh = r[h];
            float4 w0 = W4[h*3 + 0], w1 = W4[h*3 + 1], w2 = W4[h*3 + 2];
            a0.x = fmaf(rh, w0.x, a0.x); a0.y = fmaf(rh, w0.y, a0.y);
            a0.z = fmaf(rh, w0.z, a0.z); a0.w = fmaf(rh, w0.w, a0.w);
            a1.x = fmaf(rh, w1.x, a1.x); a1.y = fmaf(rh, w1.y, a1.y);
            a1.z = fmaf(rh, w1.z, a1.z); a1.w = fmaf(rh, w1.w, a1.w);
            a2.x = fmaf(rh, w2.x, a2.x); a2.y = fmaf(rh, w2.y, a2.y);
            a2.z = fmaf(rh, w2.z, a2.z); a2.w = fmaf(rh, w2.w, a2.w);
        }
        float* Lb = &L_s[(nt*HHH)*SP + m];
        Lb[0*SP] = a0.x; Lb[1*SP]  = a0.y; Lb[2*SP]  = a0.z; Lb[3*SP]  = a0.w;
        Lb[4*SP] = a1.x; Lb[5*SP]  = a1.y; Lb[6*SP]  = a1.z; Lb[7*SP]  = a1.w;
        Lb[8*SP] = a2.x; Lb[9*SP]  = a2.y; Lb[10*SP] = a2.z; Lb[11*SP] = a2.w;
    }
    __syncthreads();

    // Phase 2: softmax over m, then write fp16 probs (K-pad zeroed) to g_p
    for (int pair = warp; pair < NT*HHH; pair += 8) {
        int nt = pair / HHH, hp = pair - nt*HHH;
        float* row = &L_s[pair*SP];
        float mx = -1e30f;
        for (int m = lane; m < NNN; m += 32) mx = fmaxf(mx, row[m]);
        #pragma unroll
        for (int off = 16; off > 0; off >>= 1)
            mx = fmaxf(mx, __shfl_xor_sync(0xffffffffu, mx, off));
        float sum = 0.f;
        for (int m = lane; m < NNN; m += 32) {
            float e = __expf(row[m] - mx);
            row[m] = e;
            sum += e;
        }
        #pragma unroll
        for (int off = 16; off > 0; off >>= 1)
            sum += __shfl_xor_sync(0xffffffffu, sum, off);
        float inv = 1.f / sum;

        __half* op = g_p + ((size_t)(b*HHH + hp)*NPADR + (n0 + nt))*KPAD;
        #pragma unroll
        for (int i = 0; i < KPAD/32; i++) {
            int m = lane + i*32;
            float val = (m < NNN) ? row[m]*inv : 0.f;
            op[m] = __float2half(val);
        }
    }
}

// ---------------- PV kernel: out[b,n,h*64+d] = sum_m P[m] * V[m,d] (HMMA) -----
#define PST 40                         // smem k-stride (fp16)
#define PV_ABYTES (NPADR*PST*2)        // 16640
#define PV_BBYTES (DD*PST*2)           // 5120
#define PV_STAGE  (PV_ABYTES + PV_BBYTES)
#define PV_SMEM   (2*PV_STAGE)         // 43520

__global__ __launch_bounds__(256, 3)
void pv_kernel()
{
    extern __shared__ char psm[];
    const uint32_t sbase = (uint32_t)__cvta_generic_to_shared(psm);
    __half* smh = (__half*)psm;

    const int tid  = threadIdx.x;
    const int lane = tid & 31;
    const int warp = tid >> 5;             // 0..7 -> d-col block warp*8
    const int bh   = blockIdx.x;           // b*12 + h
    const int b    = bh / HHH;
    const int h    = bh - b*HHH;

    const __half* Ap  = g_p   + (size_t)bh*NPADR*KPAD;
    const __half* Bhp = g_vth + (size_t)bh*DD*KPAD;
    const __half* Blp = g_vtl + (size_t)bh*DD*KPAD;

    float acc[13][4];
    #pragma unroll
    for (int t = 0; t < 13; t++)
        #pragma unroll
        for (int c = 0; c < 4; c++) acc[t][c] = 0.f;

    const int NCH = KPAD/32;               // 7 k-chunks
    const int NST = 2*NCH;                 // 14 stages (term-major)

    auto issue = [&](int s) {
        int term = s / NCH;
        int k0 = (s - term*NCH) * 32;
        const __half* Bsrc = term ? Blp : Bhp;
        uint32_t buf = sbase + (uint32_t)(s & 1) * PV_STAGE;
        // A: 208 rows x 64B = 832 x 16B chunks
        #pragma unroll
        for (int it = 0; it < 4; it++) {
            int c = tid + it*256;
            if (c < NPADR*4) {
                int r = c >> 2, q = c & 3;
                uint32_t ad = buf + (uint32_t)(r*(PST*2) + q*16);
                asm volatile("cp.async.cg.shared.global [%0], [%1], 16;"
                             :: "r"(ad), "l"(Ap + (size_t)r*KPAD + k0 + q*8));
            }
        }
        // B: 64 rows x 64B = 256 x 16B chunks
        {
            int r = tid >> 2, q = tid & 3;
            uint32_t bd = buf + PV_ABYTES + (uint32_t)(r*(PST*2) + q*16);
            asm volatile("cp.async.cg.shared.global [%0], [%1], 16;"
                         :: "r"(bd), "l"(Bsrc + (size_t)r*KPAD + k0 + q*8));
        }
        asm volatile("cp.async.commit_group;" ::: "memory");
    };

    issue(0);

    for (int s = 0; s < NST; s++) {
        if (s + 1 < NST) {
            issue(s + 1);
            asm volatile("cp.async.wait_group 1;" ::: "memory");
        } else {
            asm volatile("cp.async.wait_group 0;" ::: "memory");
        }
        __syncthreads();

        const __half* As = smh + (size_t)(s & 1) * (PV_STAGE/2);
        const __half* Bs = As + PV_ABYTES/2;

        #pragma unroll
        for (int kh = 0; kh < 32; kh += 16) {
            const __half* pb = Bs + (warp*8 + (lane>>2))*PST + kh + (lane&3)*2;
            uint32_t b0 = *(const uint32_t*)(pb);
            uint32_t b1 = *(const uint32_t*)(pb + 8);
            #pragma unroll
            for (int t = 0; t < 13; t++) {
                const __half* pa = As + (t*16 + (lane>>2))*PST + kh + (lane&3)*2;
                uint32_t a0 = *(const uint32_t*)(pa);
                uint32_t a1 = *(const uint32_t*)(pa + 8*PST);
                uint32_t a2 = *(const uint32_t*)(pa + 8);
                uint32_t a3 = *(const uint32_t*)(pa + 8*PST + 8);
                mma16816h(acc[t], a0, a1, a2, a3, b0, b1);
            }
        }
        __syncthreads();
    }

    // epilogue: split-bf16 write into g_ah/g_al
    const int ch = h*DD + warp*8 + (lane&3)*2;
    #pragma unroll
    for (int t = 0; t < 13; t++) {
        #pragma unroll
        for (int half = 0; half < 2; half++) {
            int ntok = t*16 + (lane>>2) + half*8;
            if (ntok >= NNN) continue;
            size_t off = ((size_t)b*NNN + ntok)*CC + ch;
            float ax = acc[t][half*2 + 0];
            float ay = acc[t][half*2 + 1];
            __nv_bfloat16 hx = __float2bfloat16(ax);
            __nv_bfloat16 hy = __float2bfloat16(ay);
            __nv_bfloat162 hv; hv.x = hx; hv.y = hy;
            __nv_bfloat162 lv;
            lv.x = __float2bfloat16(ax - __bfloat162float(hx));
            lv.y = __float2bfloat16(ay - __bfloat162float(hy));
            *(__nv_bfloat162*)(g_ah + off) = hv;
            *(__nv_bfloat162*)(g_al + off) = lv;
        }
    }
}

// ---------------- launcher ----------------------------------------------------
extern "C" void kernel_launch(void* const* d_in, const int* in_sizes, int n_in,
                              void* d_out, int out_size)
{
    const float* x         = (const float*)d_in[0];
    const float* qkv_w     = (const float*)d_in[1];
    const float* qkv_b     = (const float*)d_in[2];
    const float* masks     = (const float*)d_in[3];
    const float* mask_proj = (const float*)d_in[4];
    const float* mask_base = (const float*)d_in[5];
    const float* hpw       = (const float*)d_in[6];
    const float* hpb       = (const float*)d_in[7];
    const float* proj_w    = (const float*)d_in[8];
    const float* proj_b    = (const float*)d_in[9];
    float* out             = (float*)d_out;

    void *xh_p, *xl_p, *ah_p, *al_p, *qwh_p, *qwl_p, *pwh_p, *pwl_p;
    cudaGetSymbolAddress(&xh_p,  g_xh);  cudaGetSymbolAddress(&xl_p,  g_xl);
    cudaGetSymbolAddress(&ah_p,  g_ah);  cudaGetSymbolAddress(&al_p,  g_al);
    cudaGetSymbolAddress(&qwh_p, g_qwh); cudaGetSymbolAddress(&qwl_p, g_qwl);
    cudaGetSymbolAddress(&pwh_p, g_pwh); cudaGetSymbolAddress(&pwl_p, g_pwl);

    cudaFuncSetAttribute(attn_probs, cudaFuncAttributeMaxDynamicSharedMemorySize,
                         PR_SMEM_BYTES);
    cudaFuncSetAttribute(pv_kernel, cudaFuncAttributeMaxDynamicSharedMemorySize,
                         PV_SMEM);
    cudaFuncSetAttribute(tgemm<0>, cudaFuncAttributeMaxDynamicSharedMemorySize, TG2_SMEM);
    cudaFuncSetAttribute(tgemm<1>, cudaFuncAttributeMaxDynamicSharedMemorySize, TG2_SMEM);

    const int M = MROWS;               // 12608
    const int MT = (M + TGM - 1)/TGM;  // 99

    // 0) split inputs
    split_kernel<<<(M*CC + 255)/256, 256>>>(x, (__nv_bfloat16*)xh_p, (__nv_bfloat16*)xl_p, M*CC);
    wsplit_kernel<<<(CC*QKVN + 255)/256, 256>>>(qkv_w, (__nv_bfloat16*)qwh_p, (__nv_bfloat16*)qwl_p, CC, QKVN);
    wsplit_kernel<<<(CC*CC + 255)/256, 256>>>(proj_w, (__nv_bfloat16*)pwh_p, (__nv_bfloat16*)pwl_p, CC, CC);
    // 1) QKV GEMM + scatter (q,k fp32; v -> transposed fp16 split)
    {
        dim3 grid(QKVN/TGN, MT);
        tgemm<1><<<grid, 256, TG2_SMEM>>>((const __nv_bfloat16*)xh_p, (const __nv_bfloat16*)xl_p,
                                          (const __nv_bfloat16*)qwh_p, (const __nv_bfloat16*)qwl_p,
                                          qkv_b, nullptr, M, QKVN, CC);
    }
    // 2) mask weights
    mw_kernel<<<(NNN*NNN + 255)/256, 256>>>(masks, mask_proj, mask_base);
    // 3) probs -> g_p fp16
    {
        dim3 grid((NNN + NT - 1)/NT, BB);
        attn_probs<<<grid, 256, PR_SMEM_BYTES>>>(hpw, hpb);
    }
    // 4) PV via f16 HMMA -> g_ah/g_al (split bf16)
    pv_kernel<<<BB*HHH, 256, PV_SMEM>>>();
    // 5) output projection
    {
        dim3 grid(CC/TGN, MT);
        tgemm<0><<<grid, 256, TG2_SMEM>>>((const __nv_bfloat16*)ah_p, (const __nv_bfloat16*)al_p,
                                          (const __nv_bfloat16*)pwh_p, (const __nv_bfloat16*)pwl_p,
                                          proj_b, out, M, CC, CC);
    }
}

// round 13
// speedup vs baseline: 2.4319x; 1.2272x over previous
#include <cuda_runtime.h>
#include <cuda_bf16.h>
#include <cuda_fp16.h>
#include <cstdint>

// ---------------- problem constants ----------------
#define BB   64
#define NNN  197
#define CC   768
#define HHH  12
#define GHH  2
#define HRR  6
#define DD   64
#define TOTH 16
#define QKVN 1024
#define SCALE 0.125f
#define NT   4            // query rows per probs CTA
#define NPADR 208         // padded n rows in g_p
#define KPAD 224          // padded m (K dim of PV)
#define SPP  228          // padded row stride for S_s / L_s (228%32=4 -> conflict-free)
#define MROWS (BB*NNN)    // 12608

// ---------------- device scratch ----------------
__device__ float g_q [BB*GHH*NNN*DD];
__device__ float g_k [BB*GHH*NNN*DD];
__device__ __half g_mwh[NNN*NNN*HHH];         // mask weights fp16, h fastest

__device__ __half g_p  [BB*HHH*NPADR*KPAD];   // probs fp16 (K-pad zeroed)
__device__ __half g_vth[BB*HHH*DD*KPAD];      // V^T fp16 hi  [bh][d][m]
__device__ __half g_vtl[BB*HHH*DD*KPAD];      // V^T fp16 lo

// split-bf16 operands
__device__ __nv_bfloat16 g_xh[MROWS*CC], g_xl[MROWS*CC];
__device__ __nv_bfloat16 g_ah[MROWS*CC], g_al[MROWS*CC];
__device__ __nv_bfloat16 g_qwh[QKVN*CC], g_qwl[QKVN*CC];
__device__ __nv_bfloat16 g_pwh[CC*CC],  g_pwl[CC*CC];

// ---------------- split kernels ----------------
__global__ void split_kernel(const float* __restrict__ src,
                             __nv_bfloat16* __restrict__ hi,
                             __nv_bfloat16* __restrict__ lo, int n)
{
    int i = blockIdx.x*blockDim.x + threadIdx.x;
    if (i < n) {
        float v = src[i];
        __nv_bfloat16 h = __float2bfloat16(v);
        hi[i] = h;
        lo[i] = __float2bfloat16(v - __bfloat162float(h));
    }
}

__global__ void wsplit_kernel(const float* __restrict__ w,
                              __nv_bfloat16* __restrict__ hiT,
                              __nv_bfloat16* __restrict__ loT, int K, int N)
{
    int i = blockIdx.x*blockDim.x + threadIdx.x;
    if (i < K*N) {
        int k = i / N, n = i - k*N;
        float v = w[i];
        __nv_bfloat16 h = __float2bfloat16(v);
        hiT[(size_t)n*K + k] = h;
        loT[(size_t)n*K + k] = __float2bfloat16(v - __bfloat162float(h));
    }
}

// ---------------- MMA helpers ----------------
__device__ __forceinline__ void mma16816(float* d,
    uint32_t a0, uint32_t a1, uint32_t a2, uint32_t a3,
    uint32_t b0, uint32_t b1)
{
    asm volatile(
        "mma.sync.aligned.m16n8k16.row.col.f32.bf16.bf16.f32 "
        "{%0,%1,%2,%3}, {%4,%5,%6,%7}, {%8,%9}, {%0,%1,%2,%3};"
        : "+f"(d[0]), "+f"(d[1]), "+f"(d[2]), "+f"(d[3])
        : "r"(a0), "r"(a1), "r"(a2), "r"(a3), "r"(b0), "r"(b1));
}

__device__ __forceinline__ void mma16816h(float* d,
    uint32_t a0, uint32_t a1, uint32_t a2, uint32_t a3,
    uint32_t b0, uint32_t b1)
{
    asm volatile(
        "mma.sync.aligned.m16n8k16.row.col.f32.f16.f16.f32 "
        "{%0,%1,%2,%3}, {%4,%5,%6,%7}, {%8,%9}, {%0,%1,%2,%3};"
        : "+f"(d[0]), "+f"(d[1]), "+f"(d[2]), "+f"(d[3])
        : "r"(a0), "r"(a1), "r"(a2), "r"(a3), "r"(b0), "r"(b1));
}

#define LDSM_X4(r0, r1, r2, r3, addr) \
    asm volatile("ldmatrix.sync.aligned.m8n8.x4.shared.b16 {%0,%1,%2,%3}, [%4];" \
        : "=r"(r0), "=r"(r1), "=r"(r2), "=r"(r3) : "r"(addr))

// ---------------- mma.sync split-bf16 GEMM (ldmatrix fragments) ---------------
#define TGM 128
#define TGN 128
#define KS2 64
#define AST2 72
#define OPER_BYTES (TGM*AST2*2)
#define BUF_BYTES  (2*OPER_BYTES)
#define TG2_SMEM   (2*BUF_BYTES)

template<int EPI>
__global__ __launch_bounds__(256, 2)
void tgemm(const __nv_bfloat16* __restrict__ Ah, const __nv_bfloat16* __restrict__ Al,
           const __nv_bfloat16* __restrict__ Bh, const __nv_bfloat16* __restrict__ Bl,
           const float* __restrict__ bias, float* __restrict__ C,
           int M, int Nc, int K)
{
    extern __shared__ char sm2[];
    const uint32_t smem_base = (uint32_t)__cvta_generic_to_shared(sm2);

    const int tid  = threadIdx.x;
    const int lane = tid & 31;
    const int warp = tid >> 5;
    const int mw   = warp >> 2;
    const int nw   = warp & 3;
    const int g    = lane >> 2;
    const int tig  = lane & 3;

    const int rowBase = blockIdx.y * TGM;
    const int colBase = blockIdx.x * TGN;

    const int kchunks = K / KS2;
    const int nsteps  = 3 * kchunks;

    // ldmatrix lane address components
    const int lr      = lane & 7;
    const int aRowOff = ((lane >> 3) & 1) * 8 + lr;  // within m16
    const int aKoff   = (lane >> 4) * 8;             // k half for blocks 2,3
    const int bTile   = (lane >> 4) & 1;             // tile within pair
    const int bKoff   = ((lane >> 3) & 1) * 8;

    float acc[4][4][4];
    #pragma unroll
    for (int i = 0; i < 4; i++)
        #pragma unroll
        for (int j = 0; j < 4; j++)
            #pragma unroll
            for (int t = 0; t < 4; t++) acc[i][j][t] = 0.f;

    auto issue = [&](int s) {
        int term = s / kchunks;
        int k0 = (s - term*kchunks) * KS2;
        const __nv_bfloat16* Asrc = (term == 1) ? Al : Ah;
        const __nv_bfloat16* Bsrc = (term == 2) ? Bl : Bh;
        uint32_t buf = smem_base + (uint32_t)(s & 1) * BUF_BYTES;
        #pragma unroll
        for (int it = 0; it < 4; it++) {
            int c = tid + it*256;
            int r = c >> 3, col = c & 7;
            int gr = rowBase + r;
            uint32_t ad = buf + (uint32_t)(r*(AST2*2) + col*16);
            const __nv_bfloat16* srcA = Asrc + (size_t)(gr < M ? gr : 0)*K + k0 + col*8;
            int nb = (gr < M) ? 16 : 0;
            asm volatile("cp.async.cg.shared.global [%0], [%1], 16, %2;"
                         :: "r"(ad), "l"(srcA), "r"(nb));
            uint32_t bd = ad + OPER_BYTES;
            const __nv_bfloat16* srcB = Bsrc + (size_t)(colBase + r)*K + k0 + col*8;
            asm volatile("cp.async.cg.shared.global [%0], [%1], 16;"
                         :: "r"(bd), "l"(srcB));
        }
        asm volatile("cp.async.commit_group;" ::: "memory");
    };

    issue(0);

    for (int s = 0; s < nsteps; s++) {
        if (s + 1 < nsteps) {
            issue(s + 1);
            asm volatile("cp.async.wait_group 1;" ::: "memory");
        } else {
            asm volatile("cp.async.wait_group 0;" ::: "memory");
        }
        __syncthreads();

        uint32_t As_u = smem_base + (uint32_t)(s & 1) * BUF_BYTES;
        uint32_t Bs_u = As_u + OPER_BYTES;

        #pragma unroll
        for (int kh = 0; kh < KS2; kh += 16) {
            uint32_t afr[4][4], bfr[4][2];
            #pragma unroll
            for (int i = 0; i < 4; i++) {
                uint32_t ad = As_u + (uint32_t)(((mw*64 + i*16 + aRowOff)*AST2 + kh + aKoff) * 2);
                LDSM_X4(afr[i][0], afr[i][1], afr[i][2], afr[i][3], ad);
            }
            #pragma unroll
            for (int p = 0; p < 2; p++) {
                uint32_t bd = Bs_u + (uint32_t)(((nw*32 + (2*p + bTile)*8 + lr)*AST2 + kh + bKoff) * 2);
                LDSM_X4(bfr[2*p][0], bfr[2*p][1], bfr[2*p+1][0], bfr[2*p+1][1], bd);
            }
            #pragma unroll
            for (int i = 0; i < 4; i++)
                #pragma unroll
                for (int j = 0; j < 4; j++)
                    mma16816(acc[i][j], afr[i][0], afr[i][1], afr[i][2], afr[i][3],
                             bfr[j][0], bfr[j][1]);
        }
        __syncthreads();
    }

    #pragma unroll
    for (int i = 0; i < 4; i++) {
        #pragma unroll
        for (int half = 0; half < 2; half++) {
            int gr = rowBase + mw*64 + i*16 + g + half*8;
            if (gr >= M) continue;
            int bidx = 0, n = 0;
            if (EPI == 1) { bidx = gr / NNN; n = gr - bidx*NNN; }
            #pragma unroll
            for (int j = 0; j < 4; j++) {
                int gc = colBase + nw*32 + j*8 + tig*2;
                float2 v;
                v.x = acc[i][j][half*2 + 0] + bias[gc];
                v.y = acc[i][j][half*2 + 1] + bias[gc + 1];
                if (EPI == 0) {
                    *(float2*)(C + (size_t)gr*Nc + gc) = v;
                } else {
                    int t = gc >> 6, d = gc & 63;
                    if (t < GHH) {
                        *(float2*)(g_q + (((size_t)bidx*GHH + t)*NNN + n)*DD + d) = v;
                    } else if (t < 2*GHH) {
                        *(float2*)(g_k + (((size_t)bidx*GHH + (t-GHH))*NNN + n)*DD + d) = v;
                    } else {
                        int h = t - 2*GHH;
                        size_t bse = ((size_t)(bidx*HHH + h)*DD + d)*KPAD + n;
                        __half h0 = __float2half(v.x);
                        g_vth[bse] = h0;
                        g_vtl[bse] = __float2half(v.x - __half2float(h0));
                        __half h1 = __float2half(v.y);
                        g_vth[bse + KPAD] = h1;
                        g_vtl[bse + KPAD] = __float2half(v.y - __half2float(h1));
                    }
                }
            }
        }
    }
}

// ---------------- mask weights (fp16 out) ----------------
__global__ void mw_kernel(const float* __restrict__ masks,
                          const float* __restrict__ mproj,
                          const float* __restrict__ mbase)
{
    int idx = blockIdx.x * blockDim.x + threadIdx.x;
    if (idx >= NNN*NNN) return;
    float l0 = masks[(size_t)idx*3 + 0];
    float l1 = masks[(size_t)idx*3 + 1];
    float l2 = masks[(size_t)idx*3 + 2];
    #pragma unroll
    for (int h = 0; h < HHH; h++) {
        float v = l0*mproj[0*HHH + h] + l1*mproj[1*HHH + h] + l2*mproj[2*HHH + h] + mbase[h];
        g_mwh[(size_t)idx*HHH + h] = __float2half(v);
    }
}

// ---------------- probs kernel: QK + HMMA head-mix + softmax -> g_p fp16 ------
#define PR_SMEM_FLOATS (NT*GHH*DD + NT*GHH*SPP + NT*HHH*SPP + 16)
#define PR_SMEM_BYTES  (PR_SMEM_FLOATS * 4)

__global__ __launch_bounds__(256, 4)
void attn_probs(const float* __restrict__ hpw, const float* __restrict__ hpb)
{
    extern __shared__ float sm[];
    float* q_s  = sm;                         // [NT][GHH][DD]
    float* S_s  = q_s + NT*GHH*DD;            // [NT][GHH][SPP]
    float* L_s  = S_s + NT*GHH*SPP;           // [NT][HHH][SPP]
    float* hb_s = L_s + NT*HHH*SPP;           // [12]

    const int tid  = threadIdx.x;
    const int lane = tid & 31;
    const int warp = tid >> 5;                // 0..7
    const int r    = lane >> 2;               // 0..7
    const int tig  = lane & 3;                // 0..3
    const int b    = blockIdx.y;
    const int n0   = blockIdx.x * NT;
    const int nvalid = min(NT, NNN - n0);

    if (tid < 12) hb_s[tid] = hpb[tid];

    // W fragments (B operand of head-mix MMA): per lane, built once
    uint32_t wf[2][2];
    {
        int nn = r;             // n within n8 tile
        #pragma unroll
        for (int j = 0; j < 2; j++) {
            int n = j*8 + nn;
            int k0 = tig*2;
            float w00 = (n < 12) ? hpw[k0*12 + n]     : 0.f;
            float w01 = (n < 12) ? hpw[(k0+1)*12 + n] : 0.f;
            __half2 h0 = __floats2half2_rn(w00, w01);
            wf[j][0] = *(uint32_t*)&h0;
            int k1 = k0 + 8;
            float w10 = (n < 12 && k1   < 12) ? hpw[k1*12 + n]     : 0.f;
            float w11 = (n < 12 && k1+1 < 12) ? hpw[(k1+1)*12 + n] : 0.f;
            __half2 h1 = __floats2half2_rn(w10, w11);
            wf[j][1] = *(uint32_t*)&h1;
        }
    }

    for (int i = tid; i < NT*GHH*DD; i += 256) {
        int nt = i / (GHH*DD), rem = i % (GHH*DD);
        int g = rem / DD, d = rem % DD;
        q_s[(nt*GHH + g)*DD + d] = (nt < nvalid)
            ? g_q[(((size_t)b*GHH + g)*NNN + (n0 + nt))*DD + d] : 0.f;
    }
    __syncthreads();

    // Phase 1a: S (fp32), m padded to 224 with zeros
    for (int idx = tid; idx < KPAD*GHH; idx += 256) {
        int m = idx >> 1, g = idx & 1;
        float accm[NT];
        #pragma unroll
        for (int nt = 0; nt < NT; nt++) accm[nt] = 0.f;
        if (m < NNN) {
            const float4* kp = (const float4*)(g_k + (((size_t)b*GHH + g)*NNN + m)*DD);
            #pragma unroll
            for (int t = 0; t < 16; t++) {
                float4 kv = kp[t];
                #pragma unroll
                for (int nt = 0; nt < NT; nt++) {
                    float4 qv = *(const float4*)&q_s[(nt*GHH + g)*DD + t*4];
                    accm[nt] = fmaf(qv.x, kv.x, accm[nt]);
                    accm[nt] = fmaf(qv.y, kv.y, accm[nt]);
                    accm[nt] = fmaf(qv.z, kv.z, accm[nt]);
                    accm[nt] = fmaf(qv.w, kv.w, accm[nt]);
                }
            }
        }
        #pragma unroll
        for (int nt = 0; nt < NT; nt++)
            S_s[(nt*GHH + g)*SPP + m] = accm[nt] * SCALE;
    }
    __syncthreads();

    // Phase 1b: relu(s*mw) fragments -> 2 HMMA per (nt, m16-tile)
    for (int u = warp; u < NT*(KPAD/16); u += 8) {
        int nt = u / (KPAD/16), mt = u - nt*(KPAD/16);
        int n = n0 + nt; if (n >= NNN) n = NNN - 1;
        int m0 = mt*16 + r, m1 = m0 + 8;

        float s0a = S_s[(nt*GHH + 0)*SPP + m0];
        float s1a = S_s[(nt*GHH + 1)*SPP + m0];
        float s0b = S_s[(nt*GHH + 0)*SPP + m1];
        float s1b = S_s[(nt*GHH + 1)*SPP + m1];
        float slo_a = (tig < 3) ? s0a : s1a;   // h pair lo: (0,1)(2,3)(4,5)->s0, (6,7)->s1
        float slo_b = (tig < 3) ? s0b : s1b;

        float2 mlo_a = make_float2(0.f, 0.f), mlo_b = make_float2(0.f, 0.f);
        float2 mhi_a = make_float2(0.f, 0.f), mhi_b = make_float2(0.f, 0.f);
        if (m0 < NNN) {
            mlo_a = __half22float2(*(const __half2*)(g_mwh + ((size_t)n*NNN + m0)*HHH + tig*2));
            if (tig < 2)
                mhi_a = __half22float2(*(const __half2*)(g_mwh + ((size_t)n*NNN + m0)*HHH + 8 + tig*2));
        }
        if (m1 < NNN) {
            mlo_b = __half22float2(*(const __half2*)(g_mwh + ((size_t)n*NNN + m1)*HHH + tig*2));
            if (tig < 2)
                mhi_b = __half22float2(*(const __half2*)(g_mwh + ((size_t)n*NNN + m1)*HHH + 8 + tig*2));
        }

        __half2 a0h = __floats2half2_rn(fmaxf(slo_a*mlo_a.x, 0.f), fmaxf(slo_a*mlo_a.y, 0.f));
        __half2 a1h = __floats2half2_rn(fmaxf(slo_b*mlo_b.x, 0.f), fmaxf(slo_b*mlo_b.y, 0.f));
        __half2 a2h = __floats2half2_rn(fmaxf(s1a*mhi_a.x, 0.f),  fmaxf(s1a*mhi_a.y, 0.f));
        __half2 a3h = __floats2half2_rn(fmaxf(s1b*mhi_b.x, 0.f),  fmaxf(s1b*mhi_b.y, 0.f));
        uint32_t a0 = *(uint32_t*)&a0h, a1 = *(uint32_t*)&a1h;
        uint32_t a2 = *(uint32_t*)&a2h, a3 = *(uint32_t*)&a3h;

        float c0[4] = {0.f,0.f,0.f,0.f};
        float c1[4] = {0.f,0.f,0.f,0.f};
        mma16816h(c0, a0, a1, a2, a3, wf[0][0], wf[0][1]);
        mma16816h(c1, a0, a1, a2, a3, wf[1][0], wf[1][1]);

        // store logits + bias: c[0],c[1] -> (m0, hp, hp+1); c[2],c[3] -> (m1, ...)
        {
            int hp = tig*2;
            float* Lb = &L_s[(nt*HHH + hp)*SPP];
            Lb[m0]        = c0[0] + hb_s[hp];
            Lb[SPP + m0]  = c0[1] + hb_s[hp+1];
            Lb[m1]        = c0[2] + hb_s[hp];
            Lb[SPP + m1]  = c0[3] + hb_s[hp+1];
        }
        if (tig < 2) {
            int hp = 8 + tig*2;
            float* Lb = &L_s[(nt*HHH + hp)*SPP];
            Lb[m0]        = c1[0] + hb_s[hp];
            Lb[SPP + m0]  = c1[1] + hb_s[hp+1];
            Lb[m1]        = c1[2] + hb_s[hp];
            Lb[SPP + m1]  = c1[3] + hb_s[hp+1];
        }
    }
    __syncthreads();

    // Phase 2: softmax over m, write fp16 probs (K-pad zeroed)
    for (int pair = warp; pair < NT*HHH; pair += 8) {
        int nt = pair / HHH, hp = pair - nt*HHH;
        float* row = &L_s[pair*SPP];
        float mx = -1e30f;
        for (int m = lane; m < NNN; m += 32) mx = fmaxf(mx, row[m]);
        #pragma unroll
        for (int off = 16; off > 0; off >>= 1)
            mx = fmaxf(mx, __shfl_xor_sync(0xffffffffu, mx, off));
        float sum = 0.f;
        for (int m = lane; m < NNN; m += 32) {
            float e = __expf(row[m] - mx);
            row[m] = e;
            sum += e;
        }
        #pragma unroll
        for (int off = 16; off > 0; off >>= 1)
            sum += __shfl_xor_sync(0xffffffffu, sum, off);
        float inv = 1.f / sum;

        __half* op = g_p + ((size_t)(b*HHH + hp)*NPADR + (n0 + nt))*KPAD;
        #pragma unroll
        for (int i = 0; i < KPAD/32; i++) {
            int m = lane + i*32;
            float val = (m < NNN) ? row[m]*inv : 0.f;
            op[m] = __float2half(val);
        }
    }
}

// ---------------- PV kernel (unchanged from R12) ------------------------------
#define PST 40
#define PV_ABYTES (NPADR*PST*2)
#define PV_BBYTES (DD*PST*2)
#define PV_STAGE  (PV_ABYTES + PV_BBYTES)
#define PV_SMEM   (2*PV_STAGE)

__global__ __launch_bounds__(256, 3)
void pv_kernel()
{
    extern __shared__ char psm[];
    const uint32_t sbase = (uint32_t)__cvta_generic_to_shared(psm);
    __half* smh = (__half*)psm;

    const int tid  = threadIdx.x;
    const int lane = tid & 31;
    const int warp = tid >> 5;
    const int bh   = blockIdx.x;
    const int b    = bh / HHH;
    const int h    = bh - b*HHH;

    const __half* Ap  = g_p   + (size_t)bh*NPADR*KPAD;
    const __half* Bhp = g_vth + (size_t)bh*DD*KPAD;
    const __half* Blp = g_vtl + (size_t)bh*DD*KPAD;

    float acc[13][4];
    #pragma unroll
    for (int t = 0; t < 13; t++)
        #pragma unroll
        for (int c = 0; c < 4; c++) acc[t][c] = 0.f;

    const int NCH = KPAD/32;
    const int NST = 2*NCH;

    auto issue = [&](int s) {
        int term = s / NCH;
        int k0 = (s - term*NCH) * 32;
        const __half* Bsrc = term ? Blp : Bhp;
        uint32_t buf = sbase + (uint32_t)(s & 1) * PV_STAGE;
        #pragma unroll
        for (int it = 0; it < 4; it++) {
            int c = tid + it*256;
            if (c < NPADR*4) {
                int r = c >> 2, q = c & 3;
                uint32_t ad = buf + (uint32_t)(r*(PST*2) + q*16);
                asm volatile("cp.async.cg.shared.global [%0], [%1], 16;"
                             :: "r"(ad), "l"(Ap + (size_t)r*KPAD + k0 + q*8));
            }
        }
        {
            int r = tid >> 2, q = tid & 3;
            uint32_t bd = buf + PV_ABYTES + (uint32_t)(r*(PST*2) + q*16);
            asm volatile("cp.async.cg.shared.global [%0], [%1], 16;"
                         :: "r"(bd), "l"(Bsrc + (size_t)r*KPAD + k0 + q*8));
        }
        asm volatile("cp.async.commit_group;" ::: "memory");
    };

    issue(0);

    for (int s = 0; s < NST; s++) {
        if (s + 1 < NST) {
            issue(s + 1);
            asm volatile("cp.async.wait_group 1;" ::: "memory");
        } else {
            asm volatile("cp.async.wait_group 0;" ::: "memory");
        }
        __syncthreads();

        const __half* As = smh + (size_t)(s & 1) * (PV_STAGE/2);
        const __half* Bs = As + PV_ABYTES/2;

        #pragma unroll
        for (int kh = 0; kh < 32; kh += 16) {
            const __half* pb = Bs + (warp*8 + (lane>>2))*PST + kh + (lane&3)*2;
            uint32_t b0 = *(const uint32_t*)(pb);
            uint32_t b1 = *(const uint32_t*)(pb + 8);
            #pragma unroll
            for (int t = 0; t < 13; t++) {
                const __half* pa = As + (t*16 + (lane>>2))*PST + kh + (lane&3)*2;
                uint32_t a0 = *(const uint32_t*)(pa);
                uint32_t a1 = *(const uint32_t*)(pa + 8*PST);
                uint32_t a2 = *(const uint32_t*)(pa + 8);
                uint32_t a3 = *(const uint32_t*)(pa + 8*PST + 8);
                mma16816h(acc[t], a0, a1, a2, a3, b0, b1);
            }
        }
        __syncthreads();
    }

    const int ch = h*DD + warp*8 + (lane&3)*2;
    #pragma unroll
    for (int t = 0; t < 13; t++) {
        #pragma unroll
        for (int half = 0; half < 2; half++) {
            int ntok = t*16 + (lane>>2) + half*8;
            if (ntok >= NNN) continue;
            size_t off = ((size_t)b*NNN + ntok)*CC + ch;
            float ax = acc[t][half*2 + 0];
            float ay = acc[t][half*2 + 1];
            __nv_bfloat16 hx = __float2bfloat16(ax);
            __nv_bfloat16 hy = __float2bfloat16(ay);
            __nv_bfloat162 hv; hv.x = hx; hv.y = hy;
            __nv_bfloat162 lv;
            lv.x = __float2bfloat16(ax - __bfloat162float(hx));
            lv.y = __float2bfloat16(ay - __bfloat162float(hy));
            *(__nv_bfloat162*)(g_ah + off) = hv;
            *(__nv_bfloat162*)(g_al + off) = lv;
        }
    }
}

// ---------------- launcher ----------------------------------------------------
extern "C" void kernel_launch(void* const* d_in, const int* in_sizes, int n_in,
                              void* d_out, int out_size)
{
    const float* x         = (const float*)d_in[0];
    const float* qkv_w     = (const float*)d_in[1];
    const float* qkv_b     = (const float*)d_in[2];
    const float* masks     = (const float*)d_in[3];
    const float* mask_proj = (const float*)d_in[4];
    const float* mask_base = (const float*)d_in[5];
    const float* hpw       = (const float*)d_in[6];
    const float* hpb       = (const float*)d_in[7];
    const float* proj_w    = (const float*)d_in[8];
    const float* proj_b    = (const float*)d_in[9];
    float* out             = (float*)d_out;

    void *xh_p, *xl_p, *ah_p, *al_p, *qwh_p, *qwl_p, *pwh_p, *pwl_p;
    cudaGetSymbolAddress(&xh_p,  g_xh);  cudaGetSymbolAddress(&xl_p,  g_xl);
    cudaGetSymbolAddress(&ah_p,  g_ah);  cudaGetSymbolAddress(&al_p,  g_al);
    cudaGetSymbolAddress(&qwh_p, g_qwh); cudaGetSymbolAddress(&qwl_p, g_qwl);
    cudaGetSymbolAddress(&pwh_p, g_pwh); cudaGetSymbolAddress(&pwl_p, g_pwl);

    cudaFuncSetAttribute(attn_probs, cudaFuncAttributeMaxDynamicSharedMemorySize,
                         PR_SMEM_BYTES);
    cudaFuncSetAttribute(pv_kernel, cudaFuncAttributeMaxDynamicSharedMemorySize,
                         PV_SMEM);
    cudaFuncSetAttribute(tgemm<0>, cudaFuncAttributeMaxDynamicSharedMemorySize, TG2_SMEM);
    cudaFuncSetAttribute(tgemm<1>, cudaFuncAttributeMaxDynamicSharedMemorySize, TG2_SMEM);

    const int M = MROWS;
    const int MT = (M + TGM - 1)/TGM;

    split_kernel<<<(M*CC + 255)/256, 256>>>(x, (__nv_bfloat16*)xh_p, (__nv_bfloat16*)xl_p, M*CC);
    wsplit_kernel<<<(CC*QKVN + 255)/256, 256>>>(qkv_w, (__nv_bfloat16*)qwh_p, (__nv_bfloat16*)qwl_p, CC, QKVN);
    wsplit_kernel<<<(CC*CC + 255)/256, 256>>>(proj_w, (__nv_bfloat16*)pwh_p, (__nv_bfloat16*)pwl_p, CC, CC);
    {
        dim3 grid(QKVN/TGN, MT);
        tgemm<1><<<grid, 256, TG2_SMEM>>>((const __nv_bfloat16*)xh_p, (const __nv_bfloat16*)xl_p,
                                          (const __nv_bfloat16*)qwh_p, (const __nv_bfloat16*)qwl_p,
                                          qkv_b, nullptr, M, QKVN, CC);
    }
    mw_kernel<<<(NNN*NNN + 255)/256, 256>>>(masks, mask_proj, mask_base);
    {
        dim3 grid((NNN + NT - 1)/NT, BB);
        attn_probs<<<grid, 256, PR_SMEM_BYTES>>>(hpw, hpb);
    }
    pv_kernel<<<BB*HHH, 256, PV_SMEM>>>();
    {
        dim3 grid(CC/TGN, MT);
        tgemm<0><<<grid, 256, TG2_SMEM>>>((const __nv_bfloat16*)ah_p, (const __nv_bfloat16*)al_p,
                                          (const __nv_bfloat16*)pwh_p, (const __nv_bfloat16*)pwl_p,
                                          proj_b, out, M, CC, CC);
    }
}

// round 14
// speedup vs baseline: 2.5190x; 1.0358x over previous
#include <cuda_runtime.h>
#include <cuda_bf16.h>
#include <cuda_fp16.h>
#include <cstdint>

// ---------------- problem constants ----------------
#define BB   64
#define NNN  197
#define CC   768
#define HHH  12
#define GHH  2
#define HRR  6
#define DD   64
#define TOTH 16
#define QKVN 1024
#define SCALE 0.125f
#define NT   4            // query rows per probs CTA
#define NPADR 208         // padded n rows in g_p
#define KPAD 224          // padded m (K dim of PV)
#define SPP  228          // padded row stride for S_s / L_s
#define MROWS (BB*NNN)    // 12608

// ---------------- device scratch ----------------
__device__ float g_q [BB*GHH*NNN*DD];
__device__ float g_k [BB*GHH*NNN*DD];
__device__ __half g_mwh[NNN*NNN*HHH];         // mask weights fp16, h fastest

__device__ __half g_p  [BB*HHH*NPADR*KPAD];   // probs fp16 (K-pad zeroed)
__device__ __half g_vth[BB*HHH*DD*KPAD];      // V^T fp16 hi  [bh][d][m]
__device__ __half g_vtl[BB*HHH*DD*KPAD];      // V^T fp16 lo

// split-bf16 operands
__device__ __nv_bfloat16 g_xh[MROWS*CC], g_xl[MROWS*CC];
__device__ __nv_bfloat16 g_ah[MROWS*CC], g_al[MROWS*CC];
__device__ __nv_bfloat16 g_qwh[QKVN*CC], g_qwl[QKVN*CC];
__device__ __nv_bfloat16 g_pwh[CC*CC],  g_pwl[CC*CC];

// ---------------- split kernels ----------------
__global__ void split_kernel(const float* __restrict__ src,
                             __nv_bfloat16* __restrict__ hi,
                             __nv_bfloat16* __restrict__ lo, int n)
{
    int i = blockIdx.x*blockDim.x + threadIdx.x;
    if (i < n) {
        float v = src[i];
        __nv_bfloat16 h = __float2bfloat16(v);
        hi[i] = h;
        lo[i] = __float2bfloat16(v - __bfloat162float(h));
    }
}

__global__ void wsplit_kernel(const float* __restrict__ w,
                              __nv_bfloat16* __restrict__ hiT,
                              __nv_bfloat16* __restrict__ loT, int K, int N)
{
    int i = blockIdx.x*blockDim.x + threadIdx.x;
    if (i < K*N) {
        int k = i / N, n = i - k*N;
        float v = w[i];
        __nv_bfloat16 h = __float2bfloat16(v);
        hiT[(size_t)n*K + k] = h;
        loT[(size_t)n*K + k] = __float2bfloat16(v - __bfloat162float(h));
    }
}

// ---------------- MMA helpers ----------------
__device__ __forceinline__ void mma16816(float* d,
    uint32_t a0, uint32_t a1, uint32_t a2, uint32_t a3,
    uint32_t b0, uint32_t b1)
{
    asm volatile(
        "mma.sync.aligned.m16n8k16.row.col.f32.bf16.bf16.f32 "
        "{%0,%1,%2,%3}, {%4,%5,%6,%7}, {%8,%9}, {%0,%1,%2,%3};"
        : "+f"(d[0]), "+f"(d[1]), "+f"(d[2]), "+f"(d[3])
        : "r"(a0), "r"(a1), "r"(a2), "r"(a3), "r"(b0), "r"(b1));
}

__device__ __forceinline__ void mma16816h(float* d,
    uint32_t a0, uint32_t a1, uint32_t a2, uint32_t a3,
    uint32_t b0, uint32_t b1)
{
    asm volatile(
        "mma.sync.aligned.m16n8k16.row.col.f32.f16.f16.f32 "
        "{%0,%1,%2,%3}, {%4,%5,%6,%7}, {%8,%9}, {%0,%1,%2,%3};"
        : "+f"(d[0]), "+f"(d[1]), "+f"(d[2]), "+f"(d[3])
        : "r"(a0), "r"(a1), "r"(a2), "r"(a3), "r"(b0), "r"(b1));
}

#define LDSM_X4(r0, r1, r2, r3, addr) \
    asm volatile("ldmatrix.sync.aligned.m8n8.x4.shared.b16 {%0,%1,%2,%3}, [%4];" \
        : "=r"(r0), "=r"(r1), "=r"(r2), "=r"(r3) : "r"(addr))

// ---------------- chunk-major split-bf16 GEMM ---------------------------------
// Per K-chunk of 32: load Ah, Al, Bh, Bl tiles once (32KB), run all 3 terms:
//   acc += Ah*Bh ; acc += Ah*Bl ; acc += Al*Bh
// 24 chunks, 2-stage cp.async double buffer. CTA 128x128, 8 warps (64x32 each).
#define TGM 128
#define TGN 128
#define KS3 32
#define AST3 40                          // smem row stride bf16 (32+8)
#define TILE3_B (TGM*AST3*2)             // 10240 bytes per tile
#define STAGE3_B (4*TILE3_B)             // 40960 bytes per stage
#define TG3_SMEM (2*STAGE3_B)            // 81920 bytes

template<int EPI>
__global__ __launch_bounds__(256, 2)
void tgemm(const __nv_bfloat16* __restrict__ Ah, const __nv_bfloat16* __restrict__ Al,
           const __nv_bfloat16* __restrict__ Bh, const __nv_bfloat16* __restrict__ Bl,
           const float* __restrict__ bias, float* __restrict__ C,
           int M, int Nc, int K)
{
    extern __shared__ char sm2[];
    const uint32_t smem_base = (uint32_t)__cvta_generic_to_shared(sm2);

    const int tid  = threadIdx.x;
    const int lane = tid & 31;
    const int warp = tid >> 5;
    const int mw   = warp >> 2;
    const int nw   = warp & 3;
    const int g    = lane >> 2;
    const int tig  = lane & 3;

    const int rowBase = blockIdx.y * TGM;
    const int colBase = blockIdx.x * TGN;

    const int nchunks = K / KS3;            // 24

    // ldmatrix lane address components
    const int lr      = lane & 7;
    const int aRowOff = ((lane >> 3) & 1) * 8 + lr;
    const int aKoff   = (lane >> 4) * 8;
    const int bTile   = (lane >> 4) & 1;
    const int bKoff   = ((lane >> 3) & 1) * 8;

    float acc[4][4][4];
    #pragma unroll
    for (int i = 0; i < 4; i++)
        #pragma unroll
        for (int j = 0; j < 4; j++)
            #pragma unroll
            for (int t = 0; t < 4; t++) acc[i][j][t] = 0.f;

    // load one chunk: 4 tiles x 128 rows x 64B = 2048 x 16B, 8 per thread
    auto issue = [&](int c) {
        int k0 = c * KS3;
        uint32_t buf = smem_base + (uint32_t)(c & 1) * STAGE3_B;
        #pragma unroll
        for (int it = 0; it < 8; it++) {
            int u = tid + it*256;              // 0..2047
            int tile = u >> 9;                 // 0..3
            int idx = u & 511;
            int r = idx >> 2, q = idx & 3;
            uint32_t dst = buf + (uint32_t)tile*TILE3_B + (uint32_t)(r*(AST3*2) + q*16);
            if (tile < 2) {
                const __nv_bfloat16* Asrc = tile ? Al : Ah;
                int gr = rowBase + r;
                const __nv_bfloat16* src = Asrc + (size_t)(gr < M ? gr : 0)*K + k0 + q*8;
                int nb = (gr < M) ? 16 : 0;
                asm volatile("cp.async.cg.shared.global [%0], [%1], 16, %2;"
                             :: "r"(dst), "l"(src), "r"(nb));
            } else {
                const __nv_bfloat16* Bsrc = (tile == 3) ? Bl : Bh;
                const __nv_bfloat16* src = Bsrc + (size_t)(colBase + r)*K + k0 + q*8;
                asm volatile("cp.async.cg.shared.global [%0], [%1], 16;"
                             :: "r"(dst), "l"(src));
            }
        }
        asm volatile("cp.async.commit_group;" ::: "memory");
    };

    issue(0);

    for (int c = 0; c < nchunks; c++) {
        if (c + 1 < nchunks) {
            issue(c + 1);
            asm volatile("cp.async.wait_group 1;" ::: "memory");
        } else {
            asm volatile("cp.async.wait_group 0;" ::: "memory");
        }
        __syncthreads();

        uint32_t buf  = smem_base + (uint32_t)(c & 1) * STAGE3_B;
        uint32_t Ah_u = buf;
        uint32_t Al_u = buf + TILE3_B;
        uint32_t Bh_u = buf + 2*TILE3_B;
        uint32_t Bl_u = buf + 3*TILE3_B;

        #pragma unroll
        for (int kh = 0; kh < KS3; kh += 16) {
            uint32_t afr[4][4], bh_f[4][2], bl_f[4][2];
            // B fragments (hi and lo)
            #pragma unroll
            for (int p = 0; p < 2; p++) {
                uint32_t off = (uint32_t)(((nw*32 + (2*p + bTile)*8 + lr)*AST3 + kh + bKoff) * 2);
                LDSM_X4(bh_f[2*p][0], bh_f[2*p][1], bh_f[2*p+1][0], bh_f[2*p+1][1], Bh_u + off);
                LDSM_X4(bl_f[2*p][0], bl_f[2*p][1], bl_f[2*p+1][0], bl_f[2*p+1][1], Bl_u + off);
            }
            // A-hi fragments -> term0 (Ah*Bh) + term2 (Ah*Bl)
            #pragma unroll
            for (int i = 0; i < 4; i++) {
                uint32_t off = (uint32_t)(((mw*64 + i*16 + aRowOff)*AST3 + kh + aKoff) * 2);
                LDSM_X4(afr[i][0], afr[i][1], afr[i][2], afr[i][3], Ah_u + off);
            }
            #pragma unroll
            for (int i = 0; i < 4; i++)
                #pragma unroll
                for (int j = 0; j < 4; j++)
                    mma16816(acc[i][j], afr[i][0], afr[i][1], afr[i][2], afr[i][3],
                             bh_f[j][0], bh_f[j][1]);
            #pragma unroll
            for (int i = 0; i < 4; i++)
                #pragma unroll
                for (int j = 0; j < 4; j++)
                    mma16816(acc[i][j], afr[i][0], afr[i][1], afr[i][2], afr[i][3],
                             bl_f[j][0], bl_f[j][1]);
            // A-lo fragments (overwrite) -> term1 (Al*Bh)
            #pragma unroll
            for (int i = 0; i < 4; i++) {
                uint32_t off = (uint32_t)(((mw*64 + i*16 + aRowOff)*AST3 + kh + aKoff) * 2);
                LDSM_X4(afr[i][0], afr[i][1], afr[i][2], afr[i][3], Al_u + off);
            }
            #pragma unroll
            for (int i = 0; i < 4; i++)
                #pragma unroll
                for (int j = 0; j < 4; j++)
                    mma16816(acc[i][j], afr[i][0], afr[i][1], afr[i][2], afr[i][3],
                             bh_f[j][0], bh_f[j][1]);
        }
        __syncthreads();
    }

    #pragma unroll
    for (int i = 0; i < 4; i++) {
        #pragma unroll
        for (int half = 0; half < 2; half++) {
            int gr = rowBase + mw*64 + i*16 + g + half*8;
            if (gr >= M) continue;
            int bidx = 0, n = 0;
            if (EPI == 1) { bidx = gr / NNN; n = gr - bidx*NNN; }
            #pragma unroll
            for (int j = 0; j < 4; j++) {
                int gc = colBase + nw*32 + j*8 + tig*2;
                float2 v;
                v.x = acc[i][j][half*2 + 0] + bias[gc];
                v.y = acc[i][j][half*2 + 1] + bias[gc + 1];
                if (EPI == 0) {
                    *(float2*)(C + (size_t)gr*Nc + gc) = v;
                } else {
                    int t = gc >> 6, d = gc & 63;
                    if (t < GHH) {
                        *(float2*)(g_q + (((size_t)bidx*GHH + t)*NNN + n)*DD + d) = v;
                    } else if (t < 2*GHH) {
                        *(float2*)(g_k + (((size_t)bidx*GHH + (t-GHH))*NNN + n)*DD + d) = v;
                    } else {
                        int h = t - 2*GHH;
                        size_t bse = ((size_t)(bidx*HHH + h)*DD + d)*KPAD + n;
                        __half h0 = __float2half(v.x);
                        g_vth[bse] = h0;
                        g_vtl[bse] = __float2half(v.x - __half2float(h0));
                        __half h1 = __float2half(v.y);
                        g_vth[bse + KPAD] = h1;
                        g_vtl[bse + KPAD] = __float2half(v.y - __half2float(h1));
                    }
                }
            }
        }
    }
}

// ---------------- mask weights (fp16 out) ----------------
__global__ void mw_kernel(const float* __restrict__ masks,
                          const float* __restrict__ mproj,
                          const float* __restrict__ mbase)
{
    int idx = blockIdx.x * blockDim.x + threadIdx.x;
    if (idx >= NNN*NNN) return;
    float l0 = masks[(size_t)idx*3 + 0];
    float l1 = masks[(size_t)idx*3 + 1];
    float l2 = masks[(size_t)idx*3 + 2];
    #pragma unroll
    for (int h = 0; h < HHH; h++) {
        float v = l0*mproj[0*HHH + h] + l1*mproj[1*HHH + h] + l2*mproj[2*HHH + h] + mbase[h];
        g_mwh[(size_t)idx*HHH + h] = __float2half(v);
    }
}

// ---------------- probs kernel (unchanged from R13) ---------------------------
#define PR_SMEM_FLOATS (NT*GHH*DD + NT*GHH*SPP + NT*HHH*SPP + 16)
#define PR_SMEM_BYTES  (PR_SMEM_FLOATS * 4)

__global__ __launch_bounds__(256, 4)
void attn_probs(const float* __restrict__ hpw, const float* __restrict__ hpb)
{
    extern __shared__ float sm[];
    float* q_s  = sm;
    float* S_s  = q_s + NT*GHH*DD;
    float* L_s  = S_s + NT*GHH*SPP;
    float* hb_s = L_s + NT*HHH*SPP;

    const int tid  = threadIdx.x;
    const int lane = tid & 31;
    const int warp = tid >> 5;
    const int r    = lane >> 2;
    const int tig  = lane & 3;
    const int b    = blockIdx.y;
    const int n0   = blockIdx.x * NT;
    const int nvalid = min(NT, NNN - n0);

    if (tid < 12) hb_s[tid] = hpb[tid];

    uint32_t wf[2][2];
    {
        int nn = r;
        #pragma unroll
        for (int j = 0; j < 2; j++) {
            int n = j*8 + nn;
            int k0 = tig*2;
            float w00 = (n < 12) ? hpw[k0*12 + n]     : 0.f;
            float w01 = (n < 12) ? hpw[(k0+1)*12 + n] : 0.f;
            __half2 h0 = __floats2half2_rn(w00, w01);
            wf[j][0] = *(uint32_t*)&h0;
            int k1 = k0 + 8;
            float w10 = (n < 12 && k1   < 12) ? hpw[k1*12 + n]     : 0.f;
            float w11 = (n < 12 && k1+1 < 12) ? hpw[(k1+1)*12 + n] : 0.f;
            __half2 h1 = __floats2half2_rn(w10, w11);
            wf[j][1] = *(uint32_t*)&h1;
        }
    }

    for (int i = tid; i < NT*GHH*DD; i += 256) {
        int nt = i / (GHH*DD), rem = i % (GHH*DD);
        int g = rem / DD, d = rem % DD;
        q_s[(nt*GHH + g)*DD + d] = (nt < nvalid)
            ? g_q[(((size_t)b*GHH + g)*NNN + (n0 + nt))*DD + d] : 0.f;
    }
    __syncthreads();

    for (int idx = tid; idx < KPAD*GHH; idx += 256) {
        int m = idx >> 1, g = idx & 1;
        float accm[NT];
        #pragma unroll
        for (int nt = 0; nt < NT; nt++) accm[nt] = 0.f;
        if (m < NNN) {
            const float4* kp = (const float4*)(g_k + (((size_t)b*GHH + g)*NNN + m)*DD);
            #pragma unroll
            for (int t = 0; t < 16; t++) {
                float4 kv = kp[t];
                #pragma unroll
                for (int nt = 0; nt < NT; nt++) {
                    float4 qv = *(const float4*)&q_s[(nt*GHH + g)*DD + t*4];
                    accm[nt] = fmaf(qv.x, kv.x, accm[nt]);
                    accm[nt] = fmaf(qv.y, kv.y, accm[nt]);
                    accm[nt] = fmaf(qv.z, kv.z, accm[nt]);
                    accm[nt] = fmaf(qv.w, kv.w, accm[nt]);
                }
            }
        }
        #pragma unroll
        for (int nt = 0; nt < NT; nt++)
            S_s[(nt*GHH + g)*SPP + m] = accm[nt] * SCALE;
    }
    __syncthreads();

    for (int u = warp; u < NT*(KPAD/16); u += 8) {
        int nt = u / (KPAD/16), mt = u - nt*(KPAD/16);
        int n = n0 + nt; if (n >= NNN) n = NNN - 1;
        int m0 = mt*16 + r, m1 = m0 + 8;

        float s0a = S_s[(nt*GHH + 0)*SPP + m0];
        float s1a = S_s[(nt*GHH + 1)*SPP + m0];
        float s0b = S_s[(nt*GHH + 0)*SPP + m1];
        float s1b = S_s[(nt*GHH + 1)*SPP + m1];
        float slo_a = (tig < 3) ? s0a : s1a;
        float slo_b = (tig < 3) ? s0b : s1b;

        float2 mlo_a = make_float2(0.f, 0.f), mlo_b = make_float2(0.f, 0.f);
        float2 mhi_a = make_float2(0.f, 0.f), mhi_b = make_float2(0.f, 0.f);
        if (m0 < NNN) {
            mlo_a = __half22float2(*(const __half2*)(g_mwh + ((size_t)n*NNN + m0)*HHH + tig*2));
            if (tig < 2)
                mhi_a = __half22float2(*(const __half2*)(g_mwh + ((size_t)n*NNN + m0)*HHH + 8 + tig*2));
        }
        if (m1 < NNN) {
            mlo_b = __half22float2(*(const __half2*)(g_mwh + ((size_t)n*NNN + m1)*HHH + tig*2));
            if (tig < 2)
                mhi_b = __half22float2(*(const __half2*)(g_mwh + ((size_t)n*NNN + m1)*HHH + 8 + tig*2));
        }

        __half2 a0h = __floats2half2_rn(fmaxf(slo_a*mlo_a.x, 0.f), fmaxf(slo_a*mlo_a.y, 0.f));
        __half2 a1h = __floats2half2_rn(fmaxf(slo_b*mlo_b.x, 0.f), fmaxf(slo_b*mlo_b.y, 0.f));
        __half2 a2h = __floats2half2_rn(fmaxf(s1a*mhi_a.x, 0.f),  fmaxf(s1a*mhi_a.y, 0.f));
        __half2 a3h = __floats2half2_rn(fmaxf(s1b*mhi_b.x, 0.f),  fmaxf(s1b*mhi_b.y, 0.f));
        uint32_t a0 = *(uint32_t*)&a0h, a1 = *(uint32_t*)&a1h;
        uint32_t a2 = *(uint32_t*)&a2h, a3 = *(uint32_t*)&a3h;

        float c0[4] = {0.f,0.f,0.f,0.f};
        float c1[4] = {0.f,0.f,0.f,0.f};
        mma16816h(c0, a0, a1, a2, a3, wf[0][0], wf[0][1]);
        mma16816h(c1, a0, a1, a2, a3, wf[1][0], wf[1][1]);

        {
            int hp = tig*2;
            float* Lb = &L_s[(nt*HHH + hp)*SPP];
            Lb[m0]        = c0[0] + hb_s[hp];
            Lb[SPP + m0]  = c0[1] + hb_s[hp+1];
            Lb[m1]        = c0[2] + hb_s[hp];
            Lb[SPP + m1]  = c0[3] + hb_s[hp+1];
        }
        if (tig < 2) {
            int hp = 8 + tig*2;
            float* Lb = &L_s[(nt*HHH + hp)*SPP];
            Lb[m0]        = c1[0] + hb_s[hp];
            Lb[SPP + m0]  = c1[1] + hb_s[hp+1];
            Lb[m1]        = c1[2] + hb_s[hp];
            Lb[SPP + m1]  = c1[3] + hb_s[hp+1];
        }
    }
    __syncthreads();

    for (int pair = warp; pair < NT*HHH; pair += 8) {
        int nt = pair / HHH, hp = pair - nt*HHH;
        float* row = &L_s[pair*SPP];
        float mx = -1e30f;
        for (int m = lane; m < NNN; m += 32) mx = fmaxf(mx, row[m]);
        #pragma unroll
        for (int off = 16; off > 0; off >>= 1)
            mx = fmaxf(mx, __shfl_xor_sync(0xffffffffu, mx, off));
        float sum = 0.f;
        for (int m = lane; m < NNN; m += 32) {
            float e = __expf(row[m] - mx);
            row[m] = e;
            sum += e;
        }
        #pragma unroll
        for (int off = 16; off > 0; off >>= 1)
            sum += __shfl_xor_sync(0xffffffffu, sum, off);
        float inv = 1.f / sum;

        __half* op = g_p + ((size_t)(b*HHH + hp)*NPADR + (n0 + nt))*KPAD;
        #pragma unroll
        for (int i = 0; i < KPAD/32; i++) {
            int m = lane + i*32;
            float val = (m < NNN) ? row[m]*inv : 0.f;
            op[m] = __float2half(val);
        }
    }
}

// ---------------- PV kernel (unchanged) ---------------------------------------
#define PST 40
#define PV_ABYTES (NPADR*PST*2)
#define PV_BBYTES (DD*PST*2)
#define PV_STAGE  (PV_ABYTES + PV_BBYTES)
#define PV_SMEM   (2*PV_STAGE)

__global__ __launch_bounds__(256, 3)
void pv_kernel()
{
    extern __shared__ char psm[];
    const uint32_t sbase = (uint32_t)__cvta_generic_to_shared(psm);
    __half* smh = (__half*)psm;

    const int tid  = threadIdx.x;
    const int lane = tid & 31;
    const int warp = tid >> 5;
    const int bh   = blockIdx.x;
    const int b    = bh / HHH;
    const int h    = bh - b*HHH;

    const __half* Ap  = g_p   + (size_t)bh*NPADR*KPAD;
    const __half* Bhp = g_vth + (size_t)bh*DD*KPAD;
    const __half* Blp = g_vtl + (size_t)bh*DD*KPAD;

    float acc[13][4];
    #pragma unroll
    for (int t = 0; t < 13; t++)
        #pragma unroll
        for (int c = 0; c < 4; c++) acc[t][c] = 0.f;

    const int NCH = KPAD/32;
    const int NST = 2*NCH;

    auto issue = [&](int s) {
        int term = s / NCH;
        int k0 = (s - term*NCH) * 32;
        const __half* Bsrc = term ? Blp : Bhp;
        uint32_t buf = sbase + (uint32_t)(s & 1) * PV_STAGE;
        #pragma unroll
        for (int it = 0; it < 4; it++) {
            int c = tid + it*256;
            if (c < NPADR*4) {
                int r = c >> 2, q = c & 3;
                uint32_t ad = buf + (uint32_t)(r*(PST*2) + q*16);
                asm volatile("cp.async.cg.shared.global [%0], [%1], 16;"
                             :: "r"(ad), "l"(Ap + (size_t)r*KPAD + k0 + q*8));
            }
        }
        {
            int r = tid >> 2, q = tid & 3;
            uint32_t bd = buf + PV_ABYTES + (uint32_t)(r*(PST*2) + q*16);
            asm volatile("cp.async.cg.shared.global [%0], [%1], 16;"
                         :: "r"(bd), "l"(Bsrc + (size_t)r*KPAD + k0 + q*8));
        }
        asm volatile("cp.async.commit_group;" ::: "memory");
    };

    issue(0);

    for (int s = 0; s < NST; s++) {
        if (s + 1 < NST) {
            issue(s + 1);
            asm volatile("cp.async.wait_group 1;" ::: "memory");
        } else {
            asm volatile("cp.async.wait_group 0;" ::: "memory");
        }
        __syncthreads();

        const __half* As = smh + (size_t)(s & 1) * (PV_STAGE/2);
        const __half* Bs = As + PV_ABYTES/2;

        #pragma unroll
        for (int kh = 0; kh < 32; kh += 16) {
            const __half* pb = Bs + (warp*8 + (lane>>2))*PST + kh + (lane&3)*2;
            uint32_t b0 = *(const uint32_t*)(pb);
            uint32_t b1 = *(const uint32_t*)(pb + 8);
            #pragma unroll
            for (int t = 0; t < 13; t++) {
                const __half* pa = As + (t*16 + (lane>>2))*PST + kh + (lane&3)*2;
                uint32_t a0 = *(const uint32_t*)(pa);
                uint32_t a1 = *(const uint32_t*)(pa + 8*PST);
                uint32_t a2 = *(const uint32_t*)(pa + 8);
                uint32_t a3 = *(const uint32_t*)(pa + 8*PST + 8);
                mma16816h(acc[t], a0, a1, a2, a3, b0, b1);
            }
        }
        __syncthreads();
    }

    const int ch = h*DD + warp*8 + (lane&3)*2;
    #pragma unroll
    for (int t = 0; t < 13; t++) {
        #pragma unroll
        for (int half = 0; half < 2; half++) {
            int ntok = t*16 + (lane>>2) + half*8;
            if (ntok >= NNN) continue;
            size_t off = ((size_t)b*NNN + ntok)*CC + ch;
            float ax = acc[t][half*2 + 0];
            float ay = acc[t][half*2 + 1];
            __nv_bfloat16 hx = __float2bfloat16(ax);
            __nv_bfloat16 hy = __float2bfloat16(ay);
            __nv_bfloat162 hv; hv.x = hx; hv.y = hy;
            __nv_bfloat162 lv;
            lv.x = __float2bfloat16(ax - __bfloat162float(hx));
            lv.y = __float2bfloat16(ay - __bfloat162float(hy));
            *(__nv_bfloat162*)(g_ah + off) = hv;
            *(__nv_bfloat162*)(g_al + off) = lv;
        }
    }
}

// ---------------- launcher ----------------------------------------------------
extern "C" void kernel_launch(void* const* d_in, const int* in_sizes, int n_in,
                              void* d_out, int out_size)
{
    const float* x         = (const float*)d_in[0];
    const float* qkv_w     = (const float*)d_in[1];
    const float* qkv_b     = (const float*)d_in[2];
    const float* masks     = (const float*)d_in[3];
    const float* mask_proj = (const float*)d_in[4];
    const float* mask_base = (const float*)d_in[5];
    const float* hpw       = (const float*)d_in[6];
    const float* hpb       = (const float*)d_in[7];
    const float* proj_w    = (const float*)d_in[8];
    const float* proj_b    = (const float*)d_in[9];
    float* out             = (float*)d_out;

    void *xh_p, *xl_p, *ah_p, *al_p, *qwh_p, *qwl_p, *pwh_p, *pwl_p;
    cudaGetSymbolAddress(&xh_p,  g_xh);  cudaGetSymbolAddress(&xl_p,  g_xl);
    cudaGetSymbolAddress(&ah_p,  g_ah);  cudaGetSymbolAddress(&al_p,  g_al);
    cudaGetSymbolAddress(&qwh_p, g_qwh); cudaGetSymbolAddress(&qwl_p, g_qwl);
    cudaGetSymbolAddress(&pwh_p, g_pwh); cudaGetSymbolAddress(&pwl_p, g_pwl);

    cudaFuncSetAttribute(attn_probs, cudaFuncAttributeMaxDynamicSharedMemorySize,
                         PR_SMEM_BYTES);
    cudaFuncSetAttribute(pv_kernel, cudaFuncAttributeMaxDynamicSharedMemorySize,
                         PV_SMEM);
    cudaFuncSetAttribute(tgemm<0>, cudaFuncAttributeMaxDynamicSharedMemorySize, TG3_SMEM);
    cudaFuncSetAttribute(tgemm<1>, cudaFuncAttributeMaxDynamicSharedMemorySize, TG3_SMEM);

    const int M = MROWS;
    const int MT = (M + TGM - 1)/TGM;

    split_kernel<<<(M*CC + 255)/256, 256>>>(x, (__nv_bfloat16*)xh_p, (__nv_bfloat16*)xl_p, M*CC);
    wsplit_kernel<<<(CC*QKVN + 255)/256, 256>>>(qkv_w, (__nv_bfloat16*)qwh_p, (__nv_bfloat16*)qwl_p, CC, QKVN);
    wsplit_kernel<<<(CC*CC + 255)/256, 256>>>(proj_w, (__nv_bfloat16*)pwh_p, (__nv_bfloat16*)pwl_p, CC, CC);
    {
        dim3 grid(QKVN/TGN, MT);
        tgemm<1><<<grid, 256, TG3_SMEM>>>((const __nv_bfloat16*)xh_p, (const __nv_bfloat16*)xl_p,
                                          (const __nv_bfloat16*)qwh_p, (const __nv_bfloat16*)qwl_p,
                                          qkv_b, nullptr, M, QKVN, CC);
    }
    mw_kernel<<<(NNN*NNN + 255)/256, 256>>>(masks, mask_proj, mask_base);
    {
        dim3 grid((NNN + NT - 1)/NT, BB);
        attn_probs<<<grid, 256, PR_SMEM_BYTES>>>(hpw, hpb);
    }
    pv_kernel<<<BB*HHH, 256, PV_SMEM>>>();
    {
        dim3 grid(CC/TGN, MT);
        tgemm<0><<<grid, 256, TG3_SMEM>>>((const __nv_bfloat16*)ah_p, (const __nv_bfloat16*)al_p,
                                          (const __nv_bfloat16*)pwh_p, (const __nv_bfloat16*)pwl_p,
                                          proj_b, out, M, CC, CC);
    }
}

// round 15
// speedup vs baseline: 4.0754x; 1.6179x over previous
#include <cuda_runtime.h>
#include <cuda_bf16.h>
#include <cuda_fp16.h>
#include <cstdint>

// ---------------- problem constants ----------------
#define BB   64
#define NNN  197
#define CC   768
#define HHH  12
#define GHH  2
#define HRR  6
#define DD   64
#define TOTH 16
#define QKVN 1024
#define SCALE 0.125f
#define NT   4            // query rows per probs CTA
#define NPADR 208         // padded n rows in g_p
#define KPAD 224          // padded m (K dim of PV)
#define SPP  228          // padded row stride for S_s / L_s
#define MROWS (BB*NNN)    // 12608

// ---------------- device scratch ----------------
__device__ float g_q [BB*GHH*NNN*DD];
__device__ float g_k [BB*GHH*NNN*DD];
__device__ __half g_mwh[NNN*NNN*HHH];         // mask weights fp16, h fastest

__device__ __half g_p  [BB*HHH*NPADR*KPAD];   // probs fp16 (K-pad zeroed)
__device__ __half g_vt [BB*HHH*DD*KPAD];      // V^T fp16  [bh][d][m]

// fp16 GEMM operands (single term)
__device__ __half g_x16[MROWS*CC];            // x fp16
__device__ __half g_a16[MROWS*CC];            // attention output fp16
__device__ __half g_qw16[QKVN*CC];            // qkv_w^T fp16  [N][K]
__device__ __half g_pw16[CC*CC];              // proj_w^T fp16 [N][K]

// ---------------- convert kernels ----------------
__global__ void tohalf_kernel(const float* __restrict__ src,
                              __half* __restrict__ dst, int n)
{
    int i = blockIdx.x*blockDim.x + threadIdx.x;
    if (i < n) dst[i] = __float2half(src[i]);
}

// transpose + convert: w is [K][N] row-major -> out [N][K] fp16
__global__ void wtrans_kernel(const float* __restrict__ w,
                              __half* __restrict__ dstT, int K, int N)
{
    int i = blockIdx.x*blockDim.x + threadIdx.x;
    if (i < K*N) {
        int k = i / N, n = i - k*N;
        dstT[(size_t)n*K + k] = __float2half(w[i]);
    }
}

// ---------------- MMA helpers ----------------
__device__ __forceinline__ void mma16816h(float* d,
    uint32_t a0, uint32_t a1, uint32_t a2, uint32_t a3,
    uint32_t b0, uint32_t b1)
{
    asm volatile(
        "mma.sync.aligned.m16n8k16.row.col.f32.f16.f16.f32 "
        "{%0,%1,%2,%3}, {%4,%5,%6,%7}, {%8,%9}, {%0,%1,%2,%3};"
        : "+f"(d[0]), "+f"(d[1]), "+f"(d[2]), "+f"(d[3])
        : "r"(a0), "r"(a1), "r"(a2), "r"(a3), "r"(b0), "r"(b1));
}

#define LDSM_X4(r0, r1, r2, r3, addr) \
    asm volatile("ldmatrix.sync.aligned.m8n8.x4.shared.b16 {%0,%1,%2,%3}, [%4];" \
        : "=r"(r0), "=r"(r1), "=r"(r2), "=r"(r3) : "r"(addr))

// ---------------- single-term fp16 GEMM ---------------------------------------
// D = A*B^T (fp16 operands, fp32 accum). B stored [N][K] K-major.
// CTA 128x128, 8 warps (64x32 each), K-step 64, 2-stage cp.async pipeline.
// EPI==0: C = D + bias   EPI==1: scatter into g_q/g_k (fp32) and g_vt (fp16^T)
#define TGM 128
#define TGN 128
#define KS4 64
#define AST4 72                          // smem row stride fp16 (64 + 8 pad)
#define OP4_BYTES (TGM*AST4*2)           // 18432 per operand per stage
#define STG4_BYTES (2*OP4_BYTES)         // A + B per stage
#define TG4_SMEM   (2*STG4_BYTES)        // 73728 bytes

template<int EPI>
__global__ __launch_bounds__(256, 2)
void tgemm(const __half* __restrict__ A, const __half* __restrict__ Bw,
           const float* __restrict__ bias, float* __restrict__ C,
           int M, int Nc, int K)
{
    extern __shared__ char sm2[];
    const uint32_t smem_base = (uint32_t)__cvta_generic_to_shared(sm2);

    const int tid  = threadIdx.x;
    const int lane = tid & 31;
    const int warp = tid >> 5;
    const int mw   = warp >> 2;
    const int nw   = warp & 3;
    const int g    = lane >> 2;
    const int tig  = lane & 3;

    const int rowBase = blockIdx.y * TGM;
    const int colBase = blockIdx.x * TGN;

    const int nchunks = K / KS4;            // 12

    // ldmatrix lane address components
    const int lr      = lane & 7;
    const int aRowOff = ((lane >> 3) & 1) * 8 + lr;
    const int aKoff   = (lane >> 4) * 8;
    const int bTile   = (lane >> 4) & 1;
    const int bKoff   = ((lane >> 3) & 1) * 8;

    float acc[4][4][4];
    #pragma unroll
    for (int i = 0; i < 4; i++)
        #pragma unroll
        for (int j = 0; j < 4; j++)
            #pragma unroll
            for (int t = 0; t < 4; t++) acc[i][j][t] = 0.f;

    // load one chunk: 2 tiles x 128 rows x 128B = 2048 x 16B, 8 per thread
    auto issue = [&](int c) {
        int k0 = c * KS4;
        uint32_t buf = smem_base + (uint32_t)(c & 1) * STG4_BYTES;
        #pragma unroll
        for (int it = 0; it < 4; it++) {
            int u = tid + it*256;              // 0..1023
            int r = u >> 3, q = u & 7;
            int gr = rowBase + r;
            uint32_t ad = buf + (uint32_t)(r*(AST4*2) + q*16);
            const __half* srcA = A + (size_t)(gr < M ? gr : 0)*K + k0 + q*8;
            int nb = (gr < M) ? 16 : 0;
            asm volatile("cp.async.cg.shared.global [%0], [%1], 16, %2;"
                         :: "r"(ad), "l"(srcA), "r"(nb));
            uint32_t bd = ad + OP4_BYTES;
            const __half* srcB = Bw + (size_t)(colBase + r)*K + k0 + q*8;
            asm volatile("cp.async.cg.shared.global [%0], [%1], 16;"
                         :: "r"(bd), "l"(srcB));
        }
        asm volatile("cp.async.commit_group;" ::: "memory");
    };

    issue(0);

    for (int c = 0; c < nchunks; c++) {
        if (c + 1 < nchunks) {
            issue(c + 1);
            asm volatile("cp.async.wait_group 1;" ::: "memory");
        } else {
            asm volatile("cp.async.wait_group 0;" ::: "memory");
        }
        __syncthreads();

        uint32_t As_u = smem_base + (uint32_t)(c & 1) * STG4_BYTES;
        uint32_t Bs_u = As_u + OP4_BYTES;

        #pragma unroll
        for (int kh = 0; kh < KS4; kh += 16) {
            uint32_t afr[4][4], bfr[4][2];
            #pragma unroll
            for (int i = 0; i < 4; i++) {
                uint32_t ad = As_u + (uint32_t)(((mw*64 + i*16 + aRowOff)*AST4 + kh + aKoff) * 2);
                LDSM_X4(afr[i][0], afr[i][1], afr[i][2], afr[i][3], ad);
            }
            #pragma unroll
            for (int p = 0; p < 2; p++) {
                uint32_t bd = Bs_u + (uint32_t)(((nw*32 + (2*p + bTile)*8 + lr)*AST4 + kh + bKoff) * 2);
                LDSM_X4(bfr[2*p][0], bfr[2*p][1], bfr[2*p+1][0], bfr[2*p+1][1], bd);
            }
            #pragma unroll
            for (int i = 0; i < 4; i++)
                #pragma unroll
                for (int j = 0; j < 4; j++)
                    mma16816h(acc[i][j], afr[i][0], afr[i][1], afr[i][2], afr[i][3],
                              bfr[j][0], bfr[j][1]);
        }
        __syncthreads();
    }

    #pragma unroll
    for (int i = 0; i < 4; i++) {
        #pragma unroll
        for (int half = 0; half < 2; half++) {
            int gr = rowBase + mw*64 + i*16 + g + half*8;
            if (gr >= M) continue;
            int bidx = 0, n = 0;
            if (EPI == 1) { bidx = gr / NNN; n = gr - bidx*NNN; }
            #pragma unroll
            for (int j = 0; j < 4; j++) {
                int gc = colBase + nw*32 + j*8 + tig*2;
                float2 v;
                v.x = acc[i][j][half*2 + 0] + bias[gc];
                v.y = acc[i][j][half*2 + 1] + bias[gc + 1];
                if (EPI == 0) {
                    *(float2*)(C + (size_t)gr*Nc + gc) = v;
                } else {
                    int t = gc >> 6, d = gc & 63;
                    if (t < GHH) {
                        *(float2*)(g_q + (((size_t)bidx*GHH + t)*NNN + n)*DD + d) = v;
                    } else if (t < 2*GHH) {
                        *(float2*)(g_k + (((size_t)bidx*GHH + (t-GHH))*NNN + n)*DD + d) = v;
                    } else {
                        int h = t - 2*GHH;
                        size_t bse = ((size_t)(bidx*HHH + h)*DD + d)*KPAD + n;
                        g_vt[bse]        = __float2half(v.x);
                        g_vt[bse + KPAD] = __float2half(v.y);
                    }
                }
            }
        }
    }
}

// ---------------- mask weights (fp16 out) ----------------
__global__ void mw_kernel(const float* __restrict__ masks,
                          const float* __restrict__ mproj,
                          const float* __restrict__ mbase)
{
    int idx = blockIdx.x * blockDim.x + threadIdx.x;
    if (idx >= NNN*NNN) return;
    float l0 = masks[(size_t)idx*3 + 0];
    float l1 = masks[(size_t)idx*3 + 1];
    float l2 = masks[(size_t)idx*3 + 2];
    #pragma unroll
    for (int h = 0; h < HHH; h++) {
        float v = l0*mproj[0*HHH + h] + l1*mproj[1*HHH + h] + l2*mproj[2*HHH + h] + mbase[h];
        g_mwh[(size_t)idx*HHH + h] = __float2half(v);
    }
}

// ---------------- probs kernel (unchanged from R13/R14) -----------------------
#define PR_SMEM_FLOATS (NT*GHH*DD + NT*GHH*SPP + NT*HHH*SPP + 16)
#define PR_SMEM_BYTES  (PR_SMEM_FLOATS * 4)

__global__ __launch_bounds__(256, 4)
void attn_probs(const float* __restrict__ hpw, const float* __restrict__ hpb)
{
    extern __shared__ float sm[];
    float* q_s  = sm;
    float* S_s  = q_s + NT*GHH*DD;
    float* L_s  = S_s + NT*GHH*SPP;
    float* hb_s = L_s + NT*HHH*SPP;

    const int tid  = threadIdx.x;
    const int lane = tid & 31;
    const int warp = tid >> 5;
    const int r    = lane >> 2;
    const int tig  = lane & 3;
    const int b    = blockIdx.y;
    const int n0   = blockIdx.x * NT;
    const int nvalid = min(NT, NNN - n0);

    if (tid < 12) hb_s[tid] = hpb[tid];

    uint32_t wf[2][2];
    {
        int nn = r;
        #pragma unroll
        for (int j = 0; j < 2; j++) {
            int n = j*8 + nn;
            int k0 = tig*2;
            float w00 = (n < 12) ? hpw[k0*12 + n]     : 0.f;
            float w01 = (n < 12) ? hpw[(k0+1)*12 + n] : 0.f;
            __half2 h0 = __floats2half2_rn(w00, w01);
            wf[j][0] = *(uint32_t*)&h0;
            int k1 = k0 + 8;
            float w10 = (n < 12 && k1   < 12) ? hpw[k1*12 + n]     : 0.f;
            float w11 = (n < 12 && k1+1 < 12) ? hpw[(k1+1)*12 + n] : 0.f;
            __half2 h1 = __floats2half2_rn(w10, w11);
            wf[j][1] = *(uint32_t*)&h1;
        }
    }

    for (int i = tid; i < NT*GHH*DD; i += 256) {
        int nt = i / (GHH*DD), rem = i % (GHH*DD);
        int g = rem / DD, d = rem % DD;
        q_s[(nt*GHH + g)*DD + d] = (nt < nvalid)
            ? g_q[(((size_t)b*GHH + g)*NNN + (n0 + nt))*DD + d] : 0.f;
    }
    __syncthreads();

    for (int idx = tid; idx < KPAD*GHH; idx += 256) {
        int m = idx >> 1, g = idx & 1;
        float accm[NT];
        #pragma unroll
        for (int nt = 0; nt < NT; nt++) accm[nt] = 0.f;
        if (m < NNN) {
            const float4* kp = (const float4*)(g_k + (((size_t)b*GHH + g)*NNN + m)*DD);
            #pragma unroll
            for (int t = 0; t < 16; t++) {
                float4 kv = kp[t];
                #pragma unroll
                for (int nt = 0; nt < NT; nt++) {
                    float4 qv = *(const float4*)&q_s[(nt*GHH + g)*DD + t*4];
                    accm[nt] = fmaf(qv.x, kv.x, accm[nt]);
                    accm[nt] = fmaf(qv.y, kv.y, accm[nt]);
                    accm[nt] = fmaf(qv.z, kv.z, accm[nt]);
                    accm[nt] = fmaf(qv.w, kv.w, accm[nt]);
                }
            }
        }
        #pragma unroll
        for (int nt = 0; nt < NT; nt++)
            S_s[(nt*GHH + g)*SPP + m] = accm[nt] * SCALE;
    }
    __syncthreads();

    for (int u = warp; u < NT*(KPAD/16); u += 8) {
        int nt = u / (KPAD/16), mt = u - nt*(KPAD/16);
        int n = n0 + nt; if (n >= NNN) n = NNN - 1;
        int m0 = mt*16 + r, m1 = m0 + 8;

        float s0a = S_s[(nt*GHH + 0)*SPP + m0];
        float s1a = S_s[(nt*GHH + 1)*SPP + m0];
        float s0b = S_s[(nt*GHH + 0)*SPP + m1];
        float s1b = S_s[(nt*GHH + 1)*SPP + m1];
        float slo_a = (tig < 3) ? s0a : s1a;
        float slo_b = (tig < 3) ? s0b : s1b;

        float2 mlo_a = make_float2(0.f, 0.f), mlo_b = make_float2(0.f, 0.f);
        float2 mhi_a = make_float2(0.f, 0.f), mhi_b = make_float2(0.f, 0.f);
        if (m0 < NNN) {
            mlo_a = __half22float2(*(const __half2*)(g_mwh + ((size_t)n*NNN + m0)*HHH + tig*2));
            if (tig < 2)
                mhi_a = __half22float2(*(const __half2*)(g_mwh + ((size_t)n*NNN + m0)*HHH + 8 + tig*2));
        }
        if (m1 < NNN) {
            mlo_b = __half22float2(*(const __half2*)(g_mwh + ((size_t)n*NNN + m1)*HHH + tig*2));
            if (tig < 2)
                mhi_b = __half22float2(*(const __half2*)(g_mwh + ((size_t)n*NNN + m1)*HHH + 8 + tig*2));
        }

        __half2 a0h = __floats2half2_rn(fmaxf(slo_a*mlo_a.x, 0.f), fmaxf(slo_a*mlo_a.y, 0.f));
        __half2 a1h = __floats2half2_rn(fmaxf(slo_b*mlo_b.x, 0.f), fmaxf(slo_b*mlo_b.y, 0.f));
        __half2 a2h = __floats2half2_rn(fmaxf(s1a*mhi_a.x, 0.f),  fmaxf(s1a*mhi_a.y, 0.f));
        __half2 a3h = __floats2half2_rn(fmaxf(s1b*mhi_b.x, 0.f),  fmaxf(s1b*mhi_b.y, 0.f));
        uint32_t a0 = *(uint32_t*)&a0h, a1 = *(uint32_t*)&a1h;
        uint32_t a2 = *(uint32_t*)&a2h, a3 = *(uint32_t*)&a3h;

        float c0[4] = {0.f,0.f,0.f,0.f};
        float c1[4] = {0.f,0.f,0.f,0.f};
        mma16816h(c0, a0, a1, a2, a3, wf[0][0], wf[0][1]);
        mma16816h(c1, a0, a1, a2, a3, wf[1][0], wf[1][1]);

        {
            int hp = tig*2;
            float* Lb = &L_s[(nt*HHH + hp)*SPP];
            Lb[m0]        = c0[0] + hb_s[hp];
            Lb[SPP + m0]  = c0[1] + hb_s[hp+1];
            Lb[m1]        = c0[2] + hb_s[hp];
            Lb[SPP + m1]  = c0[3] + hb_s[hp+1];
        }
        if (tig < 2) {
            int hp = 8 + tig*2;
            float* Lb = &L_s[(nt*HHH + hp)*SPP];
            Lb[m0]        = c1[0] + hb_s[hp];
            Lb[SPP + m0]  = c1[1] + hb_s[hp+1];
            Lb[m1]        = c1[2] + hb_s[hp];
            Lb[SPP + m1]  = c1[3] + hb_s[hp+1];
        }
    }
    __syncthreads();

    for (int pair = warp; pair < NT*HHH; pair += 8) {
        int nt = pair / HHH, hp = pair - nt*HHH;
        float* row = &L_s[pair*SPP];
        float mx = -1e30f;
        for (int m = lane; m < NNN; m += 32) mx = fmaxf(mx, row[m]);
        #pragma unroll
        for (int off = 16; off > 0; off >>= 1)
            mx = fmaxf(mx, __shfl_xor_sync(0xffffffffu, mx, off));
        float sum = 0.f;
        for (int m = lane; m < NNN; m += 32) {
            float e = __expf(row[m] - mx);
            row[m] = e;
            sum += e;
        }
        #pragma unroll
        for (int off = 16; off > 0; off >>= 1)
            sum += __shfl_xor_sync(0xffffffffu, sum, off);
        float inv = 1.f / sum;

        __half* op = g_p + ((size_t)(b*HHH + hp)*NPADR + (n0 + nt))*KPAD;
        #pragma unroll
        for (int i = 0; i < KPAD/32; i++) {
            int m = lane + i*32;
            float val = (m < NNN) ? row[m]*inv : 0.f;
            op[m] = __float2half(val);
        }
    }
}

// ---------------- PV kernel (single V term) -----------------------------------
#define PST 40
#define PV_ABYTES (NPADR*PST*2)
#define PV_BBYTES (DD*PST*2)
#define PV_STAGE  (PV_ABYTES + PV_BBYTES)
#define PV_SMEM   (2*PV_STAGE)

__global__ __launch_bounds__(256, 3)
void pv_kernel()
{
    extern __shared__ char psm[];
    const uint32_t sbase = (uint32_t)__cvta_generic_to_shared(psm);
    __half* smh = (__half*)psm;

    const int tid  = threadIdx.x;
    const int lane = tid & 31;
    const int warp = tid >> 5;
    const int bh   = blockIdx.x;
    const int b    = bh / HHH;
    const int h    = bh - b*HHH;

    const __half* Ap = g_p  + (size_t)bh*NPADR*KPAD;
    const __half* Bp = g_vt + (size_t)bh*DD*KPAD;

    float acc[13][4];
    #pragma unroll
    for (int t = 0; t < 13; t++)
        #pragma unroll
        for (int c = 0; c < 4; c++) acc[t][c] = 0.f;

    const int NST = KPAD/32;               // 7 stages

    auto issue = [&](int s) {
        int k0 = s * 32;
        uint32_t buf = sbase + (uint32_t)(s & 1) * PV_STAGE;
        #pragma unroll
        for (int it = 0; it < 4; it++) {
            int c = tid + it*256;
            if (c < NPADR*4) {
                int r = c >> 2, q = c & 3;
                uint32_t ad = buf + (uint32_t)(r*(PST*2) + q*16);
                asm volatile("cp.async.cg.shared.global [%0], [%1], 16;"
                             :: "r"(ad), "l"(Ap + (size_t)r*KPAD + k0 + q*8));
            }
        }
        {
            int r = tid >> 2, q = tid & 3;
            uint32_t bd = buf + PV_ABYTES + (uint32_t)(r*(PST*2) + q*16);
            asm volatile("cp.async.cg.shared.global [%0], [%1], 16;"
                         :: "r"(bd), "l"(Bp + (size_t)r*KPAD + k0 + q*8));
        }
        asm volatile("cp.async.commit_group;" ::: "memory");
    };

    issue(0);

    for (int s = 0; s < NST; s++) {
        if (s + 1 < NST) {
            issue(s + 1);
            asm volatile("cp.async.wait_group 1;" ::: "memory");
        } else {
            asm volatile("cp.async.wait_group 0;" ::: "memory");
        }
        __syncthreads();

        const __half* As = smh + (size_t)(s & 1) * (PV_STAGE/2);
        const __half* Bs = As + PV_ABYTES/2;

        #pragma unroll
        for (int kh = 0; kh < 32; kh += 16) {
            const __half* pb = Bs + (warp*8 + (lane>>2))*PST + kh + (lane&3)*2;
            uint32_t b0 = *(const uint32_t*)(pb);
            uint32_t b1 = *(const uint32_t*)(pb + 8);
            #pragma unroll
            for (int t = 0; t < 13; t++) {
                const __half* pa = As + (t*16 + (lane>>2))*PST + kh + (lane&3)*2;
                uint32_t a0 = *(const uint32_t*)(pa);
                uint32_t a1 = *(const uint32_t*)(pa + 8*PST);
                uint32_t a2 = *(const uint32_t*)(pa + 8);
                uint32_t a3 = *(const uint32_t*)(pa + 8*PST + 8);
                mma16816h(acc[t], a0, a1, a2, a3, b0, b1);
            }
        }
        __syncthreads();
    }

    // epilogue: write fp16 attention output (feeds tgemm<0>)
    const int ch = h*DD + warp*8 + (lane&3)*2;
    #pragma unroll
    for (int t = 0; t < 13; t++) {
        #pragma unroll
        for (int half = 0; half < 2; half++) {
            int ntok = t*16 + (lane>>2) + half*8;
            if (ntok >= NNN) continue;
            size_t off = ((size_t)b*NNN + ntok)*CC + ch;
            __half2 hv;
            hv.x = __float2half(acc[t][half*2 + 0]);
            hv.y = __float2half(acc[t][half*2 + 1]);
            *(__half2*)(g_a16 + off) = hv;
        }
    }
}

// ---------------- launcher ----------------------------------------------------
extern "C" void kernel_launch(void* const* d_in, const int* in_sizes, int n_in,
                              void* d_out, int out_size)
{
    const float* x         = (const float*)d_in[0];
    const float* qkv_w     = (const float*)d_in[1];
    const float* qkv_b     = (const float*)d_in[2];
    const float* masks     = (const float*)d_in[3];
    const float* mask_proj = (const float*)d_in[4];
    const float* mask_base = (const float*)d_in[5];
    const float* hpw       = (const float*)d_in[6];
    const float* hpb       = (const float*)d_in[7];
    const float* proj_w    = (const float*)d_in[8];
    const float* proj_b    = (const float*)d_in[9];
    float* out             = (float*)d_out;

    void *x16_p, *a16_p, *qw16_p, *pw16_p;
    cudaGetSymbolAddress(&x16_p,  g_x16);
    cudaGetSymbolAddress(&a16_p,  g_a16);
    cudaGetSymbolAddress(&qw16_p, g_qw16);
    cudaGetSymbolAddress(&pw16_p, g_pw16);

    cudaFuncSetAttribute(attn_probs, cudaFuncAttributeMaxDynamicSharedMemorySize,
                         PR_SMEM_BYTES);
    cudaFuncSetAttribute(pv_kernel, cudaFuncAttributeMaxDynamicSharedMemorySize,
                         PV_SMEM);
    cudaFuncSetAttribute(tgemm<0>, cudaFuncAttributeMaxDynamicSharedMemorySize, TG4_SMEM);
    cudaFuncSetAttribute(tgemm<1>, cudaFuncAttributeMaxDynamicSharedMemorySize, TG4_SMEM);

    const int M = MROWS;
    const int MT = (M + TGM - 1)/TGM;

    // 0) fp16 conversions
    tohalf_kernel<<<(M*CC + 255)/256, 256>>>(x, (__half*)x16_p, M*CC);
    wtrans_kernel<<<(CC*QKVN + 255)/256, 256>>>(qkv_w, (__half*)qw16_p, CC, QKVN);
    wtrans_kernel<<<(CC*CC + 255)/256, 256>>>(proj_w, (__half*)pw16_p, CC, CC);
    // 1) QKV GEMM (fp16 single-term) + scatter (q,k fp32; v -> g_vt fp16^T)
    {
        dim3 grid(QKVN/TGN, MT);
        tgemm<1><<<grid, 256, TG4_SMEM>>>((const __half*)x16_p, (const __half*)qw16_p,
                                          qkv_b, nullptr, M, QKVN, CC);
    }
    // 2) mask weights
    mw_kernel<<<(NNN*NNN + 255)/256, 256>>>(masks, mask_proj, mask_base);
    // 3) probs -> g_p fp16
    {
        dim3 grid((NNN + NT - 1)/NT, BB);
        attn_probs<<<grid, 256, PR_SMEM_BYTES>>>(hpw, hpb);
    }
    // 4) PV -> g_a16
    pv_kernel<<<BB*HHH, 256, PV_SMEM>>>();
    // 5) output projection (fp16 single-term)
    {
        dim3 grid(CC/TGN, MT);
        tgemm<0><<<grid, 256, TG4_SMEM>>>((const __half*)a16_p, (const __half*)pw16_p,
                                          proj_b, out, M, CC, CC);
    }
}